// round 10
// baseline (speedup 1.0000x reference)
#include <cuda_runtime.h>

static const int N_PAPER = 200000;
static const int N_MESH  = 30000;
static const int NNODES  = 230000;
static const int E_TR    = 2000000;
static const int E_P     = 500000;
static const int E_N     = 500000;
static const int NBLK_SCAN = (NNODES + 1023) / 1024;   // 225

typedef unsigned long long u64;

// ---- static device scratch ----
__device__ __align__(256) float g_x0[NNODES * 32];
__device__ __align__(256) float g_x1[NNODES * 32];
__device__ __align__(256) float g_Y[2 * NNODES * 32];   // [Y_rel0 ; Y_rel1]
__device__ __align__(256) int   g_ssel[E_TR];           // src + etype*NNODES
__device__ __align__(256) int   g_dst[E_TR];
__device__ __align__(256) int   g_eidx[E_TR];           // CSR buckets (ssel by dst)
__device__ __align__(256) int   g_cnt[NNODES];
__device__ __align__(256) int   g_rowptr[NNODES];
__device__ __align__(256) int   g_cursor[NNODES];
__device__ __align__(256) int   g_pre[NNODES];
__device__ __align__(256) int   g_bsum[NBLK_SCAN];

// ---- packed f32x2 helpers (FFMA2 is PTX-only) ----
__device__ __forceinline__ u64 pack2(float a, float b) {
    u64 r;
    asm("mov.b64 %0, {%1, %2};" : "=l"(r) : "r"(__float_as_uint(a)), "r"(__float_as_uint(b)));
    return r;
}
__device__ __forceinline__ u64 ffma2(u64 a, u64 b, u64 c) {
    u64 d;
    asm("fma.rn.f32x2 %0, %1, %2, %3;" : "=l"(d) : "l"(a), "l"(b), "l"(c));
    return d;
}
__device__ __forceinline__ float2 unpack2(u64 v) {
    unsigned lo, hi;
    asm("mov.b64 {%0, %1}, %2;" : "=r"(lo), "=r"(hi) : "l"(v));
    return make_float2(__uint_as_float(lo), __uint_as_float(hi));
}

// ---- CSR build ----
__global__ void hist_k(const int* __restrict__ ei, const int* __restrict__ et,
                       int* __restrict__ ssel, int* __restrict__ dstv, int* __restrict__ cnt)
{
    int e = blockIdx.x * blockDim.x + threadIdx.x;
    if (e >= E_TR) return;
    int s = ei[e];
    int d = ei[E_TR + e];
    int t = et[e];
    ssel[e] = s + t * NNODES;
    dstv[e] = d;
    atomicAdd(&cnt[d], 1);
}

__global__ void scan1_k(const int* __restrict__ cnt, int* __restrict__ pre, int* __restrict__ bsum)
{
    __shared__ int sh[256];
    int tid = threadIdx.x;
    int base = blockIdx.x * 1024 + tid * 4;
    int v[4];
#pragma unroll
    for (int j = 0; j < 4; j++) v[j] = (base + j < NNODES) ? cnt[base + j] : 0;
    int tsum = v[0] + v[1] + v[2] + v[3];
    sh[tid] = tsum;
    __syncthreads();
    for (int off = 1; off < 256; off <<= 1) {
        int t = (tid >= off) ? sh[tid - off] : 0;
        __syncthreads();
        sh[tid] += t;
        __syncthreads();
    }
    int run = sh[tid] - tsum;
#pragma unroll
    for (int j = 0; j < 4; j++) {
        if (base + j < NNODES) pre[base + j] = run;
        run += v[j];
    }
    if (tid == 255) bsum[blockIdx.x] = sh[255];
}

__global__ void scan2_k(int* __restrict__ bsum, int nb)
{
    __shared__ int sh[256];
    int tid = threadIdx.x;
    int v = (tid < nb) ? bsum[tid] : 0;
    sh[tid] = v;
    __syncthreads();
    for (int off = 1; off < 256; off <<= 1) {
        int t = (tid >= off) ? sh[tid - off] : 0;
        __syncthreads();
        sh[tid] += t;
        __syncthreads();
    }
    if (tid < nb) bsum[tid] = sh[tid] - v;
}

__global__ void scan3_k(const int* __restrict__ pre, const int* __restrict__ bsum,
                        int* __restrict__ rowptr, int* __restrict__ cursor)
{
    int n = blockIdx.x * blockDim.x + threadIdx.x;
    if (n >= NNODES) return;
    int rp = pre[n] + bsum[n >> 10];
    rowptr[n] = rp;
    cursor[n] = rp;
}

__global__ void scatter_k(const int* __restrict__ ssel, const int* __restrict__ dstv,
                          int* __restrict__ cursor, int* __restrict__ eidx)
{
    int e = blockIdx.x * blockDim.x + threadIdx.x;
    if (e >= E_TR) return;
    int pos = atomicAdd(&cursor[dstv[e]], 1);
    eidx[pos] = ssel[e];
}

// ---- encode: row-per-thread, synchronous KC=16 staging, 5 CTAs/SM ----
// out[row, 0:16] = x[row, 0:DIN] @ W[DIN,16] + b
template<int DIN>
__global__ void __launch_bounds__(256, 5) encode_k(const float* __restrict__ x,
                                                   const float* __restrict__ W,
                                                   const float* __restrict__ b,
                                                   float* __restrict__ out, int nrows)
{
    constexpr int KC = 16;
    constexpr int NCHUNK = DIN / KC;
    __shared__ float xt[256 * 17];
    __shared__ ulonglong2 Wc[KC * 4];
    __shared__ float bs[16];
    const ulonglong2* Wg = (const ulonglong2*)W;
    if (threadIdx.x < 16) bs[threadIdx.x] = b[threadIdx.x];

    int tid = threadIdx.x;
    int rowBase = blockIdx.x * 256;
    int row = rowBase + tid;

    u64 acc[8];
#pragma unroll
    for (int p = 0; p < 8; p++) acc[p] = 0ull;

    for (int ch = 0; ch < NCHUNK; ch++) {
        __syncthreads();
        if (tid < KC * 4) Wc[tid] = Wg[(size_t)(ch * KC) * 4 + tid];
#pragma unroll
        for (int it = 0; it < KC; it++) {
            int idx = it * 256 + tid;
            int r = idx >> 4;
            int c = idx & 15;
            int gr = rowBase + r;
            float v = (gr < nrows) ? x[(size_t)gr * DIN + ch * KC + c] : 0.f;
            xt[r * 17 + c] = v;
        }
        __syncthreads();
#pragma unroll
        for (int k = 0; k < KC; k++) {
            float xv = xt[tid * 17 + k];
            u64 xx = pack2(xv, xv);
#pragma unroll
            for (int q = 0; q < 4; q++) {
                ulonglong2 w = Wc[k * 4 + q];
                acc[2 * q]     = ffma2(xx, w.x, acc[2 * q]);
                acc[2 * q + 1] = ffma2(xx, w.y, acc[2 * q + 1]);
            }
        }
    }
    if (row >= nrows) return;
    float4* op = (float4*)(out + (size_t)row * 16);
#pragma unroll
    for (int q = 0; q < 4; q++) {
        float2 lo = unpack2(acc[2 * q]);
        float2 hi = unpack2(acc[2 * q + 1]);
        op[q] = make_float4(lo.x + bs[4 * q], lo.y + bs[4 * q + 1],
                            hi.x + bs[4 * q + 2], hi.y + bs[4 * q + 3]);
    }
}

// ---- fused node transform: computes W from comp/basis in-CTA; Y0, Y1, self ----
template<int DIN, int DOUT>
__global__ void __launch_bounds__(256) transform3_k(const float* __restrict__ xin,
                                                    const float* __restrict__ comp,
                                                    const float* __restrict__ basis,
                                                    const float* __restrict__ root,
                                                    const float* __restrict__ bias,
                                                    float* __restrict__ Ycat,
                                                    float* __restrict__ selfout)
{
    constexpr int DO2 = DOUT / 2;
    constexpr int DO4 = DOUT / 4;
    constexpr int DIO = DIN * DOUT;
    __shared__ ulonglong2 Ws4[3 * DIN * DO4];
    __shared__ u64 bs2[DO2];
    float* Wf = (float*)Ws4;
    for (int i = threadIdx.x; i < 2 * DIO; i += blockDim.x) {
        int r = i / DIO, io = i % DIO;
        float s = 0.f;
#pragma unroll
        for (int bb = 0; bb < 4; bb++) s += comp[r * 4 + bb] * basis[bb * DIO + io];
        Wf[i] = s;
    }
    for (int i = threadIdx.x; i < DIO; i += blockDim.x) Wf[2 * DIO + i] = root[i];
    if (threadIdx.x < DO2) bs2[threadIdx.x] = ((const u64*)bias)[threadIdx.x];
    __syncthreads();
    int row = blockIdx.x * blockDim.x + threadIdx.x;
    if (row >= NNODES) return;
    float xr[DIN];
    const float4* xp = (const float4*)(xin + (size_t)row * DIN);
#pragma unroll
    for (int k4 = 0; k4 < DIN / 4; k4++) {
        float4 v = xp[k4];
        xr[4*k4] = v.x; xr[4*k4+1] = v.y; xr[4*k4+2] = v.z; xr[4*k4+3] = v.w;
    }
    u64 a0[DO2], a1[DO2], a2[DO2];
#pragma unroll
    for (int p = 0; p < DO2; p++) { a0[p] = 0ull; a1[p] = 0ull; a2[p] = bs2[p]; }
#pragma unroll
    for (int k = 0; k < DIN; k++) {
        u64 xx = pack2(xr[k], xr[k]);
#pragma unroll
        for (int o = 0; o < DO4; o++) {
            ulonglong2 w0 = Ws4[k * DO4 + o];
            a0[2*o]   = ffma2(xx, w0.x, a0[2*o]);
            a0[2*o+1] = ffma2(xx, w0.y, a0[2*o+1]);
            ulonglong2 w1 = Ws4[(DIN + k) * DO4 + o];
            a1[2*o]   = ffma2(xx, w1.x, a1[2*o]);
            a1[2*o+1] = ffma2(xx, w1.y, a1[2*o+1]);
            ulonglong2 w2 = Ws4[(2 * DIN + k) * DO4 + o];
            a2[2*o]   = ffma2(xx, w2.x, a2[2*o]);
            a2[2*o+1] = ffma2(xx, w2.y, a2[2*o+1]);
        }
    }
    float4* y0 = (float4*)(Ycat + (size_t)row * DOUT);
    float4* y1 = (float4*)(Ycat + (size_t)(NNODES + row) * DOUT);
    float4* sf = (float4*)(selfout + (size_t)row * DOUT);
#pragma unroll
    for (int o = 0; o < DO4; o++) {
        float2 l0 = unpack2(a0[2*o]), h0 = unpack2(a0[2*o+1]);
        y0[o] = make_float4(l0.x, l0.y, h0.x, h0.y);
        float2 l1 = unpack2(a1[2*o]), h1 = unpack2(a1[2*o+1]);
        y1[o] = make_float4(l1.x, l1.y, h1.x, h1.y);
        float2 l2 = unpack2(a2[2*o]), h2 = unpack2(a2[2*o+1]);
        sf[o] = make_float4(l2.x, l2.y, h2.x, h2.y);
    }
}

// ---- CSR gather aggregation + fused finalize (unroll-4 for MLP) ----
template<int DOUT, bool RELU>
__global__ void __launch_bounds__(256) agg_csr_k(const int* __restrict__ rowptr,
                                                 const int* __restrict__ cnt,
                                                 const int* __restrict__ eidx,
                                                 const float* __restrict__ Y,
                                                 float* __restrict__ x)
{
    constexpr int DO4 = DOUT / 4;
    int gid = blockIdx.x * blockDim.x + threadIdx.x;
    int n = gid / DO4;
    int j = gid % DO4;
    if (n >= NNODES) return;
    int start = rowptr[n];
    int deg = cnt[n];
    const float4* Y4 = (const float4*)Y;
    float4 acc = make_float4(0.f, 0.f, 0.f, 0.f);
    int k = 0;
    for (; k + 4 <= deg; k += 4) {
        int r0 = eidx[start + k];
        int r1 = eidx[start + k + 1];
        int r2 = eidx[start + k + 2];
        int r3 = eidx[start + k + 3];
        float4 v0 = Y4[(size_t)r0 * DO4 + j];
        float4 v1 = Y4[(size_t)r1 * DO4 + j];
        float4 v2 = Y4[(size_t)r2 * DO4 + j];
        float4 v3 = Y4[(size_t)r3 * DO4 + j];
        acc.x += (v0.x + v1.x) + (v2.x + v3.x);
        acc.y += (v0.y + v1.y) + (v2.y + v3.y);
        acc.z += (v0.z + v1.z) + (v2.z + v3.z);
        acc.w += (v0.w + v1.w) + (v2.w + v3.w);
    }
    for (; k < deg; k++) {
        int r = eidx[start + k];
        float4 v = Y4[(size_t)r * DO4 + j];
        acc.x += v.x; acc.y += v.y; acc.z += v.z; acc.w += v.w;
    }
    float s = 1.0f / fmaxf((float)deg, 1.0f);
    float4* xp = (float4*)x + (size_t)n * DO4 + j;
    float4 v = *xp;
    v.x += acc.x * s; v.y += acc.y * s; v.z += acc.z * s; v.w += acc.w * s;
    if (RELU) {
        v.x = fmaxf(v.x, 0.f); v.y = fmaxf(v.y, 0.f);
        v.z = fmaxf(v.z, 0.f); v.w = fmaxf(v.w, 0.f);
    }
    *xp = v;
}

// ---- decode: merged pos+neg; score = ((z[src] @ W_t + b_t) * z[dst]).sum() ----
__global__ void __launch_bounds__(256) decode_k(const int* __restrict__ pei,
                                                const int* __restrict__ pet,
                                                const int* __restrict__ nei,
                                                const int* __restrict__ net,
                                                const float* __restrict__ z,
                                                const float* __restrict__ w0, const float* __restrict__ b0,
                                                const float* __restrict__ w1, const float* __restrict__ b1,
                                                float* __restrict__ out)
{
    __shared__ float4 Ws[128];   // [2][16][4]
    __shared__ float bs[32];
    for (int i = threadIdx.x; i < 128; i += blockDim.x)
        Ws[i] = (i < 64) ? ((const float4*)w0)[i] : ((const float4*)w1)[i - 64];
    if (threadIdx.x < 32)
        bs[threadIdx.x] = (threadIdx.x < 16) ? b0[threadIdx.x] : b1[threadIdx.x - 16];
    __syncthreads();
    int g = blockIdx.x * blockDim.x + threadIdx.x;
    if (g >= E_P + E_N) return;
    const int* ei;
    const int* et;
    int e;
    if (g < E_P) { ei = pei; et = pet; e = g; }
    else         { ei = nei; et = net; e = g - E_P; }
    int s = ei[e];
    int d = ei[E_P + e];     // E_P == E_N == stride of both arrays
    int t = et[e];
    const float4* zs4 = (const float4*)(z + (size_t)s * 16);
    const float4* zd4 = (const float4*)(z + (size_t)d * 16);
    float zs[16];
#pragma unroll
    for (int k4 = 0; k4 < 4; k4++) {
        float4 v = zs4[k4];
        zs[4*k4] = v.x; zs[4*k4+1] = v.y; zs[4*k4+2] = v.z; zs[4*k4+3] = v.w;
    }
    float4 zd[4];
#pragma unroll
    for (int k4 = 0; k4 < 4; k4++) zd[k4] = zd4[k4];
    int tb = t * 16;
    float4 acc[4];
#pragma unroll
    for (int o = 0; o < 4; o++) acc[o] = make_float4(bs[tb+4*o], bs[tb+4*o+1], bs[tb+4*o+2], bs[tb+4*o+3]);
#pragma unroll
    for (int k = 0; k < 16; k++) {
        float xv = zs[k];
#pragma unroll
        for (int o = 0; o < 4; o++) {
            float4 w = Ws[t * 64 + k * 4 + o];
            acc[o].x += xv * w.x; acc[o].y += xv * w.y;
            acc[o].z += xv * w.z; acc[o].w += xv * w.w;
        }
    }
    float sc = 0.f;
#pragma unroll
    for (int o = 0; o < 4; o++)
        sc += acc[o].x*zd[o].x + acc[o].y*zd[o].y + acc[o].z*zd[o].z + acc[o].w*zd[o].w;
    out[g] = sc;
}

extern "C" void kernel_launch(void* const* d_in, const int* in_sizes, int n_in,
                              void* d_out, int out_size)
{
    const float* x_paper = (const float*)d_in[0];
    const float* x_mesh  = (const float*)d_in[1];
    const float* tp_w = (const float*)d_in[2];
    const float* tp_b = (const float*)d_in[3];
    const float* tm_w = (const float*)d_in[4];
    const float* tm_b = (const float*)d_in[5];
    const float* comp1 = (const float*)d_in[6];
    const float* basis1 = (const float*)d_in[7];
    const float* root1 = (const float*)d_in[8];
    const float* bias1 = (const float*)d_in[9];
    const float* comp2 = (const float*)d_in[10];
    const float* basis2 = (const float*)d_in[11];
    const float* root2 = (const float*)d_in[12];
    const float* bias2 = (const float*)d_in[13];
    const float* comp3 = (const float*)d_in[14];
    const float* basis3 = (const float*)d_in[15];
    const float* root3 = (const float*)d_in[16];
    const float* bias3 = (const float*)d_in[17];
    const float* dpp_w = (const float*)d_in[18];
    const float* dpp_b = (const float*)d_in[19];
    const float* dpm_w = (const float*)d_in[20];
    const float* dpm_b = (const float*)d_in[21];
    const int* tei = (const int*)d_in[22];   // JAX x32: int32 arrays
    const int* tet = (const int*)d_in[23];
    const int* pei = (const int*)d_in[24];
    const int* pet = (const int*)d_in[25];
    const int* nei = (const int*)d_in[26];
    const int* net = (const int*)d_in[27];
    float* out = (float*)d_out;

    float *x0, *x1, *Y;
    int *ssel, *dstv, *eidx, *cnt, *rowptr, *cursor, *pre, *bsum;
    cudaGetSymbolAddress((void**)&x0, g_x0);
    cudaGetSymbolAddress((void**)&x1, g_x1);
    cudaGetSymbolAddress((void**)&Y, g_Y);
    cudaGetSymbolAddress((void**)&ssel, g_ssel);
    cudaGetSymbolAddress((void**)&dstv, g_dst);
    cudaGetSymbolAddress((void**)&eidx, g_eidx);
    cudaGetSymbolAddress((void**)&cnt, g_cnt);
    cudaGetSymbolAddress((void**)&rowptr, g_rowptr);
    cudaGetSymbolAddress((void**)&cursor, g_cursor);
    cudaGetSymbolAddress((void**)&pre, g_pre);
    cudaGetSymbolAddress((void**)&bsum, g_bsum);

    const int EB = (E_TR + 255) / 256;
    const int NB = (NNODES + 255) / 256;

    // ncu captures the 5th graph node -> keep encode_k<512> there.
    cudaMemsetAsync(cnt, 0, NNODES * sizeof(int));                       // 1
    hist_k<<<EB, 256>>>(tei, tet, ssel, dstv, cnt);                      // 2
    scan1_k<<<NBLK_SCAN, 256>>>(cnt, pre, bsum);                         // 3
    scan2_k<<<1, 256>>>(bsum, NBLK_SCAN);                                // 4
    encode_k<512><<<(N_PAPER + 255) / 256, 256>>>(x_paper, tp_w, tp_b, x0, N_PAPER);  // 5 <- profiled
    encode_k<128><<<(N_MESH + 255) / 256, 256>>>(x_mesh, tm_w, tm_b,
                                                 x0 + (size_t)N_PAPER * 16, N_MESH);  // 6
    scan3_k<<<NB, 256>>>(pre, bsum, rowptr, cursor);                     // 7
    scatter_k<<<EB, 256>>>(ssel, dstv, cursor, eidx);                    // 8

    // ---- layer 1: 16 -> 32, relu ----
    transform3_k<16, 32><<<NB, 256>>>(x0, comp1, basis1, root1, bias1, Y, x1);
    agg_csr_k<32, true><<<(NNODES * 8 + 255) / 256, 256>>>(rowptr, cnt, eidx, Y, x1);

    // ---- layer 2: 32 -> 32, relu ----
    transform3_k<32, 32><<<NB, 256>>>(x1, comp2, basis2, root2, bias2, Y, x0);
    agg_csr_k<32, true><<<(NNODES * 8 + 255) / 256, 256>>>(rowptr, cnt, eidx, Y, x0);

    // ---- layer 3: 32 -> 16, no relu -> z in x1 ----
    transform3_k<32, 16><<<NB, 256>>>(x0, comp3, basis3, root3, bias3, Y, x1);
    agg_csr_k<16, false><<<(NNODES * 4 + 255) / 256, 256>>>(rowptr, cnt, eidx, Y, x1);

    // ---- decode: merged pos+neg ----
    decode_k<<<(E_P + E_N + 255) / 256, 256>>>(pei, pet, nei, net, x1,
                                               dpp_w, dpp_b, dpm_w, dpm_b, out);
}

// round 11
// speedup vs baseline: 1.1744x; 1.1744x over previous
#include <cuda_runtime.h>

static const int N_PAPER = 200000;
static const int N_MESH  = 30000;
static const int NNODES  = 230000;
static const int E_TR    = 2000000;
static const int E_P     = 500000;
static const int E_N     = 500000;
static const int NBLK_SCAN = (NNODES + 1023) / 1024;   // 225

typedef unsigned long long u64;

// ---- static device scratch ----
__device__ __align__(256) float g_x0[NNODES * 32];
__device__ __align__(256) float g_x1[NNODES * 32];
__device__ __align__(256) float g_Y[2 * NNODES * 32];   // [Y_rel0 ; Y_rel1]
__device__ __align__(256) int   g_ssel[E_TR];           // src + etype*NNODES
__device__ __align__(256) int   g_dst[E_TR];
__device__ __align__(256) int   g_eidx[E_TR];           // CSR buckets (ssel by dst)
__device__ __align__(256) int   g_cnt[NNODES];
__device__ __align__(256) int   g_rowptr[NNODES];
__device__ __align__(256) int   g_cursor[NNODES];
__device__ __align__(256) int   g_pre[NNODES];
__device__ __align__(256) int   g_bsum[NBLK_SCAN];

// ---- packed f32x2 helpers (FFMA2 is PTX-only) ----
__device__ __forceinline__ u64 pack2(float a, float b) {
    u64 r;
    asm("mov.b64 %0, {%1, %2};" : "=l"(r) : "r"(__float_as_uint(a)), "r"(__float_as_uint(b)));
    return r;
}
__device__ __forceinline__ u64 ffma2(u64 a, u64 b, u64 c) {
    u64 d;
    asm("fma.rn.f32x2 %0, %1, %2, %3;" : "=l"(d) : "l"(a), "l"(b), "l"(c));
    return d;
}
__device__ __forceinline__ float2 unpack2(u64 v) {
    unsigned lo, hi;
    asm("mov.b64 {%0, %1}, %2;" : "=r"(lo), "=r"(hi) : "l"(v));
    return make_float2(__uint_as_float(lo), __uint_as_float(hi));
}

// ---- CSR build ----
__global__ void hist_k(const int* __restrict__ ei, const int* __restrict__ et,
                       int* __restrict__ ssel, int* __restrict__ dstv, int* __restrict__ cnt)
{
    int e = blockIdx.x * blockDim.x + threadIdx.x;
    if (e >= E_TR) return;
    int s = ei[e];
    int d = ei[E_TR + e];
    int t = et[e];
    ssel[e] = s + t * NNODES;
    dstv[e] = d;
    atomicAdd(&cnt[d], 1);
}

__global__ void scan1_k(const int* __restrict__ cnt, int* __restrict__ pre, int* __restrict__ bsum)
{
    __shared__ int sh[256];
    int tid = threadIdx.x;
    int base = blockIdx.x * 1024 + tid * 4;
    int v[4];
#pragma unroll
    for (int j = 0; j < 4; j++) v[j] = (base + j < NNODES) ? cnt[base + j] : 0;
    int tsum = v[0] + v[1] + v[2] + v[3];
    sh[tid] = tsum;
    __syncthreads();
    for (int off = 1; off < 256; off <<= 1) {
        int t = (tid >= off) ? sh[tid - off] : 0;
        __syncthreads();
        sh[tid] += t;
        __syncthreads();
    }
    int run = sh[tid] - tsum;
#pragma unroll
    for (int j = 0; j < 4; j++) {
        if (base + j < NNODES) pre[base + j] = run;
        run += v[j];
    }
    if (tid == 255) bsum[blockIdx.x] = sh[255];
}

__global__ void scan2_k(int* __restrict__ bsum, int nb)
{
    __shared__ int sh[256];
    int tid = threadIdx.x;
    int v = (tid < nb) ? bsum[tid] : 0;
    sh[tid] = v;
    __syncthreads();
    for (int off = 1; off < 256; off <<= 1) {
        int t = (tid >= off) ? sh[tid - off] : 0;
        __syncthreads();
        sh[tid] += t;
        __syncthreads();
    }
    if (tid < nb) bsum[tid] = sh[tid] - v;
}

__global__ void scan3_k(const int* __restrict__ pre, const int* __restrict__ bsum,
                        int* __restrict__ rowptr, int* __restrict__ cursor)
{
    int n = blockIdx.x * blockDim.x + threadIdx.x;
    if (n >= NNODES) return;
    int rp = pre[n] + bsum[n >> 10];
    rowptr[n] = rp;
    cursor[n] = rp;
}

__global__ void scatter_k(const int* __restrict__ ssel, const int* __restrict__ dstv,
                          int* __restrict__ cursor, int* __restrict__ eidx)
{
    int e = blockIdx.x * blockDim.x + threadIdx.x;
    if (e >= E_TR) return;
    int pos = atomicAdd(&cursor[dstv[e]], 1);
    eidx[pos] = ssel[e];
}

// ---- encode: row-per-thread, synchronous KC=32 staging, 4 CTAs/SM (r8 winner) ----
// out[row, 0:16] = x[row, 0:DIN] @ W[DIN,16] + b
template<int DIN>
__global__ void __launch_bounds__(256, 4) encode_k(const float* __restrict__ x,
                                                   const float* __restrict__ W,
                                                   const float* __restrict__ b,
                                                   float* __restrict__ out, int nrows)
{
    constexpr int KC = 32;
    constexpr int NCHUNK = DIN / KC;
    __shared__ float xt[256 * 33];
    __shared__ ulonglong2 Wc[KC * 4];
    __shared__ float bs[16];
    const ulonglong2* Wg = (const ulonglong2*)W;
    if (threadIdx.x < 16) bs[threadIdx.x] = b[threadIdx.x];

    int tid = threadIdx.x;
    int rowBase = blockIdx.x * 256;
    int row = rowBase + tid;

    u64 acc[8];
#pragma unroll
    for (int p = 0; p < 8; p++) acc[p] = 0ull;

    for (int ch = 0; ch < NCHUNK; ch++) {
        __syncthreads();
        if (tid < KC * 4) Wc[tid] = Wg[(size_t)(ch * KC) * 4 + tid];
        for (int g = 0; g < 4; g++) {
#pragma unroll
            for (int it = 0; it < 8; it++) {
                int idx = (g * 8 + it) * 256 + tid;
                int r = idx >> 5;
                int c = idx & 31;
                int gr = rowBase + r;
                float v = (gr < nrows) ? x[(size_t)gr * DIN + ch * KC + c] : 0.f;
                xt[r * 33 + c] = v;
            }
        }
        __syncthreads();
#pragma unroll
        for (int k = 0; k < KC; k++) {
            float xv = xt[tid * 33 + k];
            u64 xx = pack2(xv, xv);
#pragma unroll
            for (int q = 0; q < 4; q++) {
                ulonglong2 w = Wc[k * 4 + q];
                acc[2 * q]     = ffma2(xx, w.x, acc[2 * q]);
                acc[2 * q + 1] = ffma2(xx, w.y, acc[2 * q + 1]);
            }
        }
    }
    if (row >= nrows) return;
    float4* op = (float4*)(out + (size_t)row * 16);
#pragma unroll
    for (int q = 0; q < 4; q++) {
        float2 lo = unpack2(acc[2 * q]);
        float2 hi = unpack2(acc[2 * q + 1]);
        op[q] = make_float4(lo.x + bs[4 * q], lo.y + bs[4 * q + 1],
                            hi.x + bs[4 * q + 2], hi.y + bs[4 * q + 3]);
    }
}

// ---- fused node transform: computes W from comp/basis in-CTA; Y0, Y1, self ----
template<int DIN, int DOUT>
__global__ void __launch_bounds__(256) transform3_k(const float* __restrict__ xin,
                                                    const float* __restrict__ comp,
                                                    const float* __restrict__ basis,
                                                    const float* __restrict__ root,
                                                    const float* __restrict__ bias,
                                                    float* __restrict__ Ycat,
                                                    float* __restrict__ selfout)
{
    constexpr int DO2 = DOUT / 2;
    constexpr int DO4 = DOUT / 4;
    constexpr int DIO = DIN * DOUT;
    __shared__ ulonglong2 Ws4[3 * DIN * DO4];
    __shared__ u64 bs2[DO2];
    float* Wf = (float*)Ws4;
    for (int i = threadIdx.x; i < 2 * DIO; i += blockDim.x) {
        int r = i / DIO, io = i % DIO;
        float s = 0.f;
#pragma unroll
        for (int bb = 0; bb < 4; bb++) s += comp[r * 4 + bb] * basis[bb * DIO + io];
        Wf[i] = s;
    }
    for (int i = threadIdx.x; i < DIO; i += blockDim.x) Wf[2 * DIO + i] = root[i];
    if (threadIdx.x < DO2) bs2[threadIdx.x] = ((const u64*)bias)[threadIdx.x];
    __syncthreads();
    int row = blockIdx.x * blockDim.x + threadIdx.x;
    if (row >= NNODES) return;
    float xr[DIN];
    const float4* xp = (const float4*)(xin + (size_t)row * DIN);
#pragma unroll
    for (int k4 = 0; k4 < DIN / 4; k4++) {
        float4 v = xp[k4];
        xr[4*k4] = v.x; xr[4*k4+1] = v.y; xr[4*k4+2] = v.z; xr[4*k4+3] = v.w;
    }
    u64 a0[DO2], a1[DO2], a2[DO2];
#pragma unroll
    for (int p = 0; p < DO2; p++) { a0[p] = 0ull; a1[p] = 0ull; a2[p] = bs2[p]; }
#pragma unroll
    for (int k = 0; k < DIN; k++) {
        u64 xx = pack2(xr[k], xr[k]);
#pragma unroll
        for (int o = 0; o < DO4; o++) {
            ulonglong2 w0 = Ws4[k * DO4 + o];
            a0[2*o]   = ffma2(xx, w0.x, a0[2*o]);
            a0[2*o+1] = ffma2(xx, w0.y, a0[2*o+1]);
            ulonglong2 w1 = Ws4[(DIN + k) * DO4 + o];
            a1[2*o]   = ffma2(xx, w1.x, a1[2*o]);
            a1[2*o+1] = ffma2(xx, w1.y, a1[2*o+1]);
            ulonglong2 w2 = Ws4[(2 * DIN + k) * DO4 + o];
            a2[2*o]   = ffma2(xx, w2.x, a2[2*o]);
            a2[2*o+1] = ffma2(xx, w2.y, a2[2*o+1]);
        }
    }
    float4* y0 = (float4*)(Ycat + (size_t)row * DOUT);
    float4* y1 = (float4*)(Ycat + (size_t)(NNODES + row) * DOUT);
    float4* sf = (float4*)(selfout + (size_t)row * DOUT);
#pragma unroll
    for (int o = 0; o < DO4; o++) {
        float2 l0 = unpack2(a0[2*o]), h0 = unpack2(a0[2*o+1]);
        y0[o] = make_float4(l0.x, l0.y, h0.x, h0.y);
        float2 l1 = unpack2(a1[2*o]), h1 = unpack2(a1[2*o+1]);
        y1[o] = make_float4(l1.x, l1.y, h1.x, h1.y);
        float2 l2 = unpack2(a2[2*o]), h2 = unpack2(a2[2*o+1]);
        sf[o] = make_float4(l2.x, l2.y, h2.x, h2.y);
    }
}

// ---- CSR gather aggregation + fused finalize (unroll-4 for MLP) ----
template<int DOUT, bool RELU>
__global__ void __launch_bounds__(256) agg_csr_k(const int* __restrict__ rowptr,
                                                 const int* __restrict__ cnt,
                                                 const int* __restrict__ eidx,
                                                 const float* __restrict__ Y,
                                                 float* __restrict__ x)
{
    constexpr int DO4 = DOUT / 4;
    int gid = blockIdx.x * blockDim.x + threadIdx.x;
    int n = gid / DO4;
    int j = gid % DO4;
    if (n >= NNODES) return;
    int start = rowptr[n];
    int deg = cnt[n];
    const float4* Y4 = (const float4*)Y;
    float4 acc = make_float4(0.f, 0.f, 0.f, 0.f);
    int k = 0;
    for (; k + 4 <= deg; k += 4) {
        int r0 = eidx[start + k];
        int r1 = eidx[start + k + 1];
        int r2 = eidx[start + k + 2];
        int r3 = eidx[start + k + 3];
        float4 v0 = Y4[(size_t)r0 * DO4 + j];
        float4 v1 = Y4[(size_t)r1 * DO4 + j];
        float4 v2 = Y4[(size_t)r2 * DO4 + j];
        float4 v3 = Y4[(size_t)r3 * DO4 + j];
        acc.x += (v0.x + v1.x) + (v2.x + v3.x);
        acc.y += (v0.y + v1.y) + (v2.y + v3.y);
        acc.z += (v0.z + v1.z) + (v2.z + v3.z);
        acc.w += (v0.w + v1.w) + (v2.w + v3.w);
    }
    for (; k < deg; k++) {
        int r = eidx[start + k];
        float4 v = Y4[(size_t)r * DO4 + j];
        acc.x += v.x; acc.y += v.y; acc.z += v.z; acc.w += v.w;
    }
    float s = 1.0f / fmaxf((float)deg, 1.0f);
    float4* xp = (float4*)x + (size_t)n * DO4 + j;
    float4 v = *xp;
    v.x += acc.x * s; v.y += acc.y * s; v.z += acc.z * s; v.w += acc.w * s;
    if (RELU) {
        v.x = fmaxf(v.x, 0.f); v.y = fmaxf(v.y, 0.f);
        v.z = fmaxf(v.z, 0.f); v.w = fmaxf(v.w, 0.f);
    }
    *xp = v;
}

// ---- decode: merged pos+neg; score = ((z[src] @ W_t + b_t) * z[dst]).sum() ----
__global__ void __launch_bounds__(256) decode_k(const int* __restrict__ pei,
                                                const int* __restrict__ pet,
                                                const int* __restrict__ nei,
                                                const int* __restrict__ net,
                                                const float* __restrict__ z,
                                                const float* __restrict__ w0, const float* __restrict__ b0,
                                                const float* __restrict__ w1, const float* __restrict__ b1,
                                                float* __restrict__ out)
{
    __shared__ float4 Ws[128];   // [2][16][4]
    __shared__ float bs[32];
    for (int i = threadIdx.x; i < 128; i += blockDim.x)
        Ws[i] = (i < 64) ? ((const float4*)w0)[i] : ((const float4*)w1)[i - 64];
    if (threadIdx.x < 32)
        bs[threadIdx.x] = (threadIdx.x < 16) ? b0[threadIdx.x] : b1[threadIdx.x - 16];
    __syncthreads();
    int g = blockIdx.x * blockDim.x + threadIdx.x;
    if (g >= E_P + E_N) return;
    const int* ei;
    const int* et;
    int e;
    if (g < E_P) { ei = pei; et = pet; e = g; }
    else         { ei = nei; et = net; e = g - E_P; }
    int s = ei[e];
    int d = ei[E_P + e];     // E_P == E_N == stride of both arrays
    int t = et[e];
    const float4* zs4 = (const float4*)(z + (size_t)s * 16);
    const float4* zd4 = (const float4*)(z + (size_t)d * 16);
    float zs[16];
#pragma unroll
    for (int k4 = 0; k4 < 4; k4++) {
        float4 v = zs4[k4];
        zs[4*k4] = v.x; zs[4*k4+1] = v.y; zs[4*k4+2] = v.z; zs[4*k4+3] = v.w;
    }
    float4 zd[4];
#pragma unroll
    for (int k4 = 0; k4 < 4; k4++) zd[k4] = zd4[k4];
    int tb = t * 16;
    float4 acc[4];
#pragma unroll
    for (int o = 0; o < 4; o++) acc[o] = make_float4(bs[tb+4*o], bs[tb+4*o+1], bs[tb+4*o+2], bs[tb+4*o+3]);
#pragma unroll
    for (int k = 0; k < 16; k++) {
        float xv = zs[k];
#pragma unroll
        for (int o = 0; o < 4; o++) {
            float4 w = Ws[t * 64 + k * 4 + o];
            acc[o].x += xv * w.x; acc[o].y += xv * w.y;
            acc[o].z += xv * w.z; acc[o].w += xv * w.w;
        }
    }
    float sc = 0.f;
#pragma unroll
    for (int o = 0; o < 4; o++)
        sc += acc[o].x*zd[o].x + acc[o].y*zd[o].y + acc[o].z*zd[o].z + acc[o].w*zd[o].w;
    out[g] = sc;
}

extern "C" void kernel_launch(void* const* d_in, const int* in_sizes, int n_in,
                              void* d_out, int out_size)
{
    const float* x_paper = (const float*)d_in[0];
    const float* x_mesh  = (const float*)d_in[1];
    const float* tp_w = (const float*)d_in[2];
    const float* tp_b = (const float*)d_in[3];
    const float* tm_w = (const float*)d_in[4];
    const float* tm_b = (const float*)d_in[5];
    const float* comp1 = (const float*)d_in[6];
    const float* basis1 = (const float*)d_in[7];
    const float* root1 = (const float*)d_in[8];
    const float* bias1 = (const float*)d_in[9];
    const float* comp2 = (const float*)d_in[10];
    const float* basis2 = (const float*)d_in[11];
    const float* root2 = (const float*)d_in[12];
    const float* bias2 = (const float*)d_in[13];
    const float* comp3 = (const float*)d_in[14];
    const float* basis3 = (const float*)d_in[15];
    const float* root3 = (const float*)d_in[16];
    const float* bias3 = (const float*)d_in[17];
    const float* dpp_w = (const float*)d_in[18];
    const float* dpp_b = (const float*)d_in[19];
    const float* dpm_w = (const float*)d_in[20];
    const float* dpm_b = (const float*)d_in[21];
    const int* tei = (const int*)d_in[22];   // JAX x32: int32 arrays
    const int* tet = (const int*)d_in[23];
    const int* pei = (const int*)d_in[24];
    const int* pet = (const int*)d_in[25];
    const int* nei = (const int*)d_in[26];
    const int* net = (const int*)d_in[27];
    float* out = (float*)d_out;

    float *x0, *x1, *Y;
    int *ssel, *dstv, *eidx, *cnt, *rowptr, *cursor, *pre, *bsum;
    cudaGetSymbolAddress((void**)&x0, g_x0);
    cudaGetSymbolAddress((void**)&x1, g_x1);
    cudaGetSymbolAddress((void**)&Y, g_Y);
    cudaGetSymbolAddress((void**)&ssel, g_ssel);
    cudaGetSymbolAddress((void**)&dstv, g_dst);
    cudaGetSymbolAddress((void**)&eidx, g_eidx);
    cudaGetSymbolAddress((void**)&cnt, g_cnt);
    cudaGetSymbolAddress((void**)&rowptr, g_rowptr);
    cudaGetSymbolAddress((void**)&cursor, g_cursor);
    cudaGetSymbolAddress((void**)&pre, g_pre);
    cudaGetSymbolAddress((void**)&bsum, g_bsum);

    const int EB = (E_TR + 255) / 256;
    const int NB = (NNODES + 255) / 256;

    // ncu captures the 5th graph node -> keep encode_k<512> there.
    cudaMemsetAsync(cnt, 0, NNODES * sizeof(int));                       // 1
    hist_k<<<EB, 256>>>(tei, tet, ssel, dstv, cnt);                      // 2
    scan1_k<<<NBLK_SCAN, 256>>>(cnt, pre, bsum);                         // 3
    scan2_k<<<1, 256>>>(bsum, NBLK_SCAN);                                // 4
    encode_k<512><<<(N_PAPER + 255) / 256, 256>>>(x_paper, tp_w, tp_b, x0, N_PAPER);  // 5 <- profiled
    encode_k<128><<<(N_MESH + 255) / 256, 256>>>(x_mesh, tm_w, tm_b,
                                                 x0 + (size_t)N_PAPER * 16, N_MESH);  // 6
    scan3_k<<<NB, 256>>>(pre, bsum, rowptr, cursor);                     // 7
    scatter_k<<<EB, 256>>>(ssel, dstv, cursor, eidx);                    // 8

    // ---- layer 1: 16 -> 32, relu ----
    transform3_k<16, 32><<<NB, 256>>>(x0, comp1, basis1, root1, bias1, Y, x1);
    agg_csr_k<32, true><<<(NNODES * 8 + 255) / 256, 256>>>(rowptr, cnt, eidx, Y, x1);

    // ---- layer 2: 32 -> 32, relu ----
    transform3_k<32, 32><<<NB, 256>>>(x1, comp2, basis2, root2, bias2, Y, x0);
    agg_csr_k<32, true><<<(NNODES * 8 + 255) / 256, 256>>>(rowptr, cnt, eidx, Y, x0);

    // ---- layer 3: 32 -> 16, no relu -> z in x1 ----
    transform3_k<32, 16><<<NB, 256>>>(x0, comp3, basis3, root3, bias3, Y, x1);
    agg_csr_k<16, false><<<(NNODES * 4 + 255) / 256, 256>>>(rowptr, cnt, eidx, Y, x1);

    // ---- decode: merged pos+neg ----
    decode_k<<<(E_P + E_N + 255) / 256, 256>>>(pei, pet, nei, net, x1,
                                               dpp_w, dpp_b, dpm_w, dpm_b, out);
}

// round 12
// speedup vs baseline: 1.2685x; 1.0802x over previous
#include <cuda_runtime.h>

static const int N_PAPER = 200000;
static const int N_MESH  = 30000;
static const int NNODES  = 230000;
static const int E_TR    = 2000000;
static const int E_P     = 500000;
static const int E_N     = 500000;
static const int NBLK_SCAN = (NNODES + 1023) / 1024;   // 225

typedef unsigned long long u64;

// ---- static device scratch ----
__device__ __align__(256) float g_x0[NNODES * 32];
__device__ __align__(256) float g_x1[NNODES * 32];
__device__ __align__(256) float g_Y[2 * NNODES * 32];   // [Y_rel0 ; Y_rel1]
__device__ __align__(256) int   g_ssel[E_TR];           // src + etype*NNODES
__device__ __align__(256) int   g_dst[E_TR];
__device__ __align__(256) int   g_eidx[E_TR];           // CSR buckets (ssel by dst)
__device__ __align__(256) int   g_cnt[NNODES];
__device__ __align__(256) int   g_rowptr[NNODES];
__device__ __align__(256) int   g_cursor[NNODES];
__device__ __align__(256) int   g_pre[NNODES];
__device__ __align__(256) int   g_bsum[NBLK_SCAN];

// ---- packed f32x2 helpers (FFMA2 is PTX-only) ----
__device__ __forceinline__ u64 pack2(float a, float b) {
    u64 r;
    asm("mov.b64 %0, {%1, %2};" : "=l"(r) : "r"(__float_as_uint(a)), "r"(__float_as_uint(b)));
    return r;
}
__device__ __forceinline__ u64 ffma2(u64 a, u64 b, u64 c) {
    u64 d;
    asm("fma.rn.f32x2 %0, %1, %2, %3;" : "=l"(d) : "l"(a), "l"(b), "l"(c));
    return d;
}
__device__ __forceinline__ float2 unpack2(u64 v) {
    unsigned lo, hi;
    asm("mov.b64 {%0, %1}, %2;" : "=r"(lo), "=r"(hi) : "l"(v));
    return make_float2(__uint_as_float(lo), __uint_as_float(hi));
}

// ---- cp.async helpers ----
__device__ __forceinline__ unsigned sptr(const void* p) {
    return (unsigned)__cvta_generic_to_shared(p);
}
__device__ __forceinline__ void cpa16(unsigned dst, const void* src, int src_sz) {
    asm volatile("cp.async.cg.shared.global [%0], [%1], 16, %2;"
                 :: "r"(dst), "l"(src), "r"(src_sz));
}
__device__ __forceinline__ void cpa_commit() { asm volatile("cp.async.commit_group;"); }
__device__ __forceinline__ void cpa_wait1()  { asm volatile("cp.async.wait_group 1;"); }
__device__ __forceinline__ void cpa_wait0()  { asm volatile("cp.async.wait_group 0;"); }

// ---- CSR build ----
__global__ void hist_k(const int* __restrict__ ei, const int* __restrict__ et,
                       int* __restrict__ ssel, int* __restrict__ dstv, int* __restrict__ cnt)
{
    int e = blockIdx.x * blockDim.x + threadIdx.x;
    if (e >= E_TR) return;
    int s = ei[e];
    int d = ei[E_TR + e];
    int t = et[e];
    ssel[e] = s + t * NNODES;
    dstv[e] = d;
    atomicAdd(&cnt[d], 1);
}

__global__ void scan1_k(const int* __restrict__ cnt, int* __restrict__ pre, int* __restrict__ bsum)
{
    __shared__ int sh[256];
    int tid = threadIdx.x;
    int base = blockIdx.x * 1024 + tid * 4;
    int v[4];
#pragma unroll
    for (int j = 0; j < 4; j++) v[j] = (base + j < NNODES) ? cnt[base + j] : 0;
    int tsum = v[0] + v[1] + v[2] + v[3];
    sh[tid] = tsum;
    __syncthreads();
    for (int off = 1; off < 256; off <<= 1) {
        int t = (tid >= off) ? sh[tid - off] : 0;
        __syncthreads();
        sh[tid] += t;
        __syncthreads();
    }
    int run = sh[tid] - tsum;
#pragma unroll
    for (int j = 0; j < 4; j++) {
        if (base + j < NNODES) pre[base + j] = run;
        run += v[j];
    }
    if (tid == 255) bsum[blockIdx.x] = sh[255];
}

__global__ void scan2_k(int* __restrict__ bsum, int nb)
{
    __shared__ int sh[256];
    int tid = threadIdx.x;
    int v = (tid < nb) ? bsum[tid] : 0;
    sh[tid] = v;
    __syncthreads();
    for (int off = 1; off < 256; off <<= 1) {
        int t = (tid >= off) ? sh[tid - off] : 0;
        __syncthreads();
        sh[tid] += t;
        __syncthreads();
    }
    if (tid < nb) bsum[tid] = sh[tid] - v;
}

__global__ void scan3_k(const int* __restrict__ pre, const int* __restrict__ bsum,
                        int* __restrict__ rowptr, int* __restrict__ cursor)
{
    int n = blockIdx.x * blockDim.x + threadIdx.x;
    if (n >= NNODES) return;
    int rp = pre[n] + bsum[n >> 10];
    rowptr[n] = rp;
    cursor[n] = rp;
}

__global__ void scatter_k(const int* __restrict__ ssel, const int* __restrict__ dstv,
                          int* __restrict__ cursor, int* __restrict__ eidx)
{
    int e = blockIdx.x * blockDim.x + threadIdx.x;
    if (e >= E_TR) return;
    int pos = atomicAdd(&cursor[dstv[e]], 1);
    eidx[pos] = ssel[e];
}

// ---- encode: row-per-thread, cp.async.16 double-buffered KC=32 chunks,
//      float4-swizzled tile (c4 ^ (r&7)) read via LDS.128 ----
// out[row, 0:16] = x[row, 0:DIN] @ W[DIN,16] + b
template<int DIN>
__global__ void __launch_bounds__(256, 3) encode_k(const float* __restrict__ x,
                                                   const float* __restrict__ W,
                                                   const float* __restrict__ b,
                                                   float* __restrict__ out, int nrows)
{
    constexpr int KC = 32;
    constexpr int NCHUNK = DIN / KC;
    __shared__ float4 xt[2][256 * 8];        // [buf][row*8 + (c4 ^ (row&7))]
    __shared__ ulonglong2 Wc[2][KC * 4];
    __shared__ float bs[16];
    const ulonglong2* Wg = (const ulonglong2*)W;
    if (threadIdx.x < 16) bs[threadIdx.x] = b[threadIdx.x];

    int tid = threadIdx.x;
    int rowBase = blockIdx.x * 256;
    int row = rowBase + tid;

    auto issue = [&](int ch) {
        int buf = ch & 1;
        if (tid < KC * 4)
            cpa16(sptr(&Wc[buf][tid]), Wg + (size_t)(ch * KC) * 4 + tid, 16);
#pragma unroll
        for (int i = 0; i < 8; i++) {
            int idx = i * 256 + tid;          // 2048 float4s: c4 fastest
            int r  = idx >> 3;
            int c4 = idx & 7;
            int gr = rowBase + r;
            int grc = (gr < nrows) ? gr : 0;
            cpa16(sptr(&xt[buf][r * 8 + (c4 ^ (r & 7))]),
                  x + (size_t)grc * DIN + ch * KC + c4 * 4,
                  (gr < nrows) ? 16 : 0);
        }
        cpa_commit();
    };

    issue(0);
    u64 acc[8];
#pragma unroll
    for (int p = 0; p < 8; p++) acc[p] = 0ull;

    int sw = tid & 7;
    for (int ch = 0; ch < NCHUNK; ch++) {
        __syncthreads();   // all warps done reading the buffer issue() will overwrite
        if (ch + 1 < NCHUNK) { issue(ch + 1); cpa_wait1(); }
        else                 { cpa_wait0(); }
        __syncthreads();   // chunk ch fully arrived for all threads
        int buf = ch & 1;
#pragma unroll
        for (int c4 = 0; c4 < 8; c4++) {
            float4 xv = xt[buf][tid * 8 + (c4 ^ sw)];
            float c[4] = {xv.x, xv.y, xv.z, xv.w};
#pragma unroll
            for (int j = 0; j < 4; j++) {
                int k = c4 * 4 + j;
                u64 xx = pack2(c[j], c[j]);
#pragma unroll
                for (int q = 0; q < 4; q++) {
                    ulonglong2 w = Wc[buf][k * 4 + q];
                    acc[2 * q]     = ffma2(xx, w.x, acc[2 * q]);
                    acc[2 * q + 1] = ffma2(xx, w.y, acc[2 * q + 1]);
                }
            }
        }
    }
    if (row >= nrows) return;
    float4* op = (float4*)(out + (size_t)row * 16);
#pragma unroll
    for (int q = 0; q < 4; q++) {
        float2 lo = unpack2(acc[2 * q]);
        float2 hi = unpack2(acc[2 * q + 1]);
        op[q] = make_float4(lo.x + bs[4 * q], lo.y + bs[4 * q + 1],
                            hi.x + bs[4 * q + 2], hi.y + bs[4 * q + 3]);
    }
}

// ---- fused node transform: computes W from comp/basis in-CTA; Y0, Y1, self ----
template<int DIN, int DOUT>
__global__ void __launch_bounds__(256) transform3_k(const float* __restrict__ xin,
                                                    const float* __restrict__ comp,
                                                    const float* __restrict__ basis,
                                                    const float* __restrict__ root,
                                                    const float* __restrict__ bias,
                                                    float* __restrict__ Ycat,
                                                    float* __restrict__ selfout)
{
    constexpr int DO2 = DOUT / 2;
    constexpr int DO4 = DOUT / 4;
    constexpr int DIO = DIN * DOUT;
    __shared__ ulonglong2 Ws4[3 * DIN * DO4];
    __shared__ u64 bs2[DO2];
    float* Wf = (float*)Ws4;
    for (int i = threadIdx.x; i < 2 * DIO; i += blockDim.x) {
        int r = i / DIO, io = i % DIO;
        float s = 0.f;
#pragma unroll
        for (int bb = 0; bb < 4; bb++) s += comp[r * 4 + bb] * basis[bb * DIO + io];
        Wf[i] = s;
    }
    for (int i = threadIdx.x; i < DIO; i += blockDim.x) Wf[2 * DIO + i] = root[i];
    if (threadIdx.x < DO2) bs2[threadIdx.x] = ((const u64*)bias)[threadIdx.x];
    __syncthreads();
    int row = blockIdx.x * blockDim.x + threadIdx.x;
    if (row >= NNODES) return;
    float xr[DIN];
    const float4* xp = (const float4*)(xin + (size_t)row * DIN);
#pragma unroll
    for (int k4 = 0; k4 < DIN / 4; k4++) {
        float4 v = xp[k4];
        xr[4*k4] = v.x; xr[4*k4+1] = v.y; xr[4*k4+2] = v.z; xr[4*k4+3] = v.w;
    }
    u64 a0[DO2], a1[DO2], a2[DO2];
#pragma unroll
    for (int p = 0; p < DO2; p++) { a0[p] = 0ull; a1[p] = 0ull; a2[p] = bs2[p]; }
#pragma unroll
    for (int k = 0; k < DIN; k++) {
        u64 xx = pack2(xr[k], xr[k]);
#pragma unroll
        for (int o = 0; o < DO4; o++) {
            ulonglong2 w0 = Ws4[k * DO4 + o];
            a0[2*o]   = ffma2(xx, w0.x, a0[2*o]);
            a0[2*o+1] = ffma2(xx, w0.y, a0[2*o+1]);
            ulonglong2 w1 = Ws4[(DIN + k) * DO4 + o];
            a1[2*o]   = ffma2(xx, w1.x, a1[2*o]);
            a1[2*o+1] = ffma2(xx, w1.y, a1[2*o+1]);
            ulonglong2 w2 = Ws4[(2 * DIN + k) * DO4 + o];
            a2[2*o]   = ffma2(xx, w2.x, a2[2*o]);
            a2[2*o+1] = ffma2(xx, w2.y, a2[2*o+1]);
        }
    }
    float4* y0 = (float4*)(Ycat + (size_t)row * DOUT);
    float4* y1 = (float4*)(Ycat + (size_t)(NNODES + row) * DOUT);
    float4* sf = (float4*)(selfout + (size_t)row * DOUT);
#pragma unroll
    for (int o = 0; o < DO4; o++) {
        float2 l0 = unpack2(a0[2*o]), h0 = unpack2(a0[2*o+1]);
        y0[o] = make_float4(l0.x, l0.y, h0.x, h0.y);
        float2 l1 = unpack2(a1[2*o]), h1 = unpack2(a1[2*o+1]);
        y1[o] = make_float4(l1.x, l1.y, h1.x, h1.y);
        float2 l2 = unpack2(a2[2*o]), h2 = unpack2(a2[2*o+1]);
        sf[o] = make_float4(l2.x, l2.y, h2.x, h2.y);
    }
}

// ---- CSR gather aggregation + fused finalize (unroll-4 for MLP) ----
template<int DOUT, bool RELU>
__global__ void __launch_bounds__(256) agg_csr_k(const int* __restrict__ rowptr,
                                                 const int* __restrict__ cnt,
                                                 const int* __restrict__ eidx,
                                                 const float* __restrict__ Y,
                                                 float* __restrict__ x)
{
    constexpr int DO4 = DOUT / 4;
    int gid = blockIdx.x * blockDim.x + threadIdx.x;
    int n = gid / DO4;
    int j = gid % DO4;
    if (n >= NNODES) return;
    int start = rowptr[n];
    int deg = cnt[n];
    const float4* Y4 = (const float4*)Y;
    float4 acc = make_float4(0.f, 0.f, 0.f, 0.f);
    int k = 0;
    for (; k + 4 <= deg; k += 4) {
        int r0 = eidx[start + k];
        int r1 = eidx[start + k + 1];
        int r2 = eidx[start + k + 2];
        int r3 = eidx[start + k + 3];
        float4 v0 = Y4[(size_t)r0 * DO4 + j];
        float4 v1 = Y4[(size_t)r1 * DO4 + j];
        float4 v2 = Y4[(size_t)r2 * DO4 + j];
        float4 v3 = Y4[(size_t)r3 * DO4 + j];
        acc.x += (v0.x + v1.x) + (v2.x + v3.x);
        acc.y += (v0.y + v1.y) + (v2.y + v3.y);
        acc.z += (v0.z + v1.z) + (v2.z + v3.z);
        acc.w += (v0.w + v1.w) + (v2.w + v3.w);
    }
    for (; k < deg; k++) {
        int r = eidx[start + k];
        float4 v = Y4[(size_t)r * DO4 + j];
        acc.x += v.x; acc.y += v.y; acc.z += v.z; acc.w += v.w;
    }
    float s = 1.0f / fmaxf((float)deg, 1.0f);
    float4* xp = (float4*)x + (size_t)n * DO4 + j;
    float4 v = *xp;
    v.x += acc.x * s; v.y += acc.y * s; v.z += acc.z * s; v.w += acc.w * s;
    if (RELU) {
        v.x = fmaxf(v.x, 0.f); v.y = fmaxf(v.y, 0.f);
        v.z = fmaxf(v.z, 0.f); v.w = fmaxf(v.w, 0.f);
    }
    *xp = v;
}

// ---- decode: merged pos+neg; score = ((z[src] @ W_t + b_t) * z[dst]).sum() ----
__global__ void __launch_bounds__(256) decode_k(const int* __restrict__ pei,
                                                const int* __restrict__ pet,
                                                const int* __restrict__ nei,
                                                const int* __restrict__ net,
                                                const float* __restrict__ z,
                                                const float* __restrict__ w0, const float* __restrict__ b0,
                                                const float* __restrict__ w1, const float* __restrict__ b1,
                                                float* __restrict__ out)
{
    __shared__ float4 Ws[128];   // [2][16][4]
    __shared__ float bs[32];
    for (int i = threadIdx.x; i < 128; i += blockDim.x)
        Ws[i] = (i < 64) ? ((const float4*)w0)[i] : ((const float4*)w1)[i - 64];
    if (threadIdx.x < 32)
        bs[threadIdx.x] = (threadIdx.x < 16) ? b0[threadIdx.x] : b1[threadIdx.x - 16];
    __syncthreads();
    int g = blockIdx.x * blockDim.x + threadIdx.x;
    if (g >= E_P + E_N) return;
    const int* ei;
    const int* et;
    int e;
    if (g < E_P) { ei = pei; et = pet; e = g; }
    else         { ei = nei; et = net; e = g - E_P; }
    int s = ei[e];
    int d = ei[E_P + e];     // E_P == E_N == stride of both arrays
    int t = et[e];
    const float4* zs4 = (const float4*)(z + (size_t)s * 16);
    const float4* zd4 = (const float4*)(z + (size_t)d * 16);
    float zs[16];
#pragma unroll
    for (int k4 = 0; k4 < 4; k4++) {
        float4 v = zs4[k4];
        zs[4*k4] = v.x; zs[4*k4+1] = v.y; zs[4*k4+2] = v.z; zs[4*k4+3] = v.w;
    }
    float4 zd[4];
#pragma unroll
    for (int k4 = 0; k4 < 4; k4++) zd[k4] = zd4[k4];
    int tb = t * 16;
    float4 acc[4];
#pragma unroll
    for (int o = 0; o < 4; o++) acc[o] = make_float4(bs[tb+4*o], bs[tb+4*o+1], bs[tb+4*o+2], bs[tb+4*o+3]);
#pragma unroll
    for (int k = 0; k < 16; k++) {
        float xv = zs[k];
#pragma unroll
        for (int o = 0; o < 4; o++) {
            float4 w = Ws[t * 64 + k * 4 + o];
            acc[o].x += xv * w.x; acc[o].y += xv * w.y;
            acc[o].z += xv * w.z; acc[o].w += xv * w.w;
        }
    }
    float sc = 0.f;
#pragma unroll
    for (int o = 0; o < 4; o++)
        sc += acc[o].x*zd[o].x + acc[o].y*zd[o].y + acc[o].z*zd[o].z + acc[o].w*zd[o].w;
    out[g] = sc;
}

extern "C" void kernel_launch(void* const* d_in, const int* in_sizes, int n_in,
                              void* d_out, int out_size)
{
    const float* x_paper = (const float*)d_in[0];
    const float* x_mesh  = (const float*)d_in[1];
    const float* tp_w = (const float*)d_in[2];
    const float* tp_b = (const float*)d_in[3];
    const float* tm_w = (const float*)d_in[4];
    const float* tm_b = (const float*)d_in[5];
    const float* comp1 = (const float*)d_in[6];
    const float* basis1 = (const float*)d_in[7];
    const float* root1 = (const float*)d_in[8];
    const float* bias1 = (const float*)d_in[9];
    const float* comp2 = (const float*)d_in[10];
    const float* basis2 = (const float*)d_in[11];
    const float* root2 = (const float*)d_in[12];
    const float* bias2 = (const float*)d_in[13];
    const float* comp3 = (const float*)d_in[14];
    const float* basis3 = (const float*)d_in[15];
    const float* root3 = (const float*)d_in[16];
    const float* bias3 = (const float*)d_in[17];
    const float* dpp_w = (const float*)d_in[18];
    const float* dpp_b = (const float*)d_in[19];
    const float* dpm_w = (const float*)d_in[20];
    const float* dpm_b = (const float*)d_in[21];
    const int* tei = (const int*)d_in[22];   // JAX x32: int32 arrays
    const int* tet = (const int*)d_in[23];
    const int* pei = (const int*)d_in[24];
    const int* pet = (const int*)d_in[25];
    const int* nei = (const int*)d_in[26];
    const int* net = (const int*)d_in[27];
    float* out = (float*)d_out;

    float *x0, *x1, *Y;
    int *ssel, *dstv, *eidx, *cnt, *rowptr, *cursor, *pre, *bsum;
    cudaGetSymbolAddress((void**)&x0, g_x0);
    cudaGetSymbolAddress((void**)&x1, g_x1);
    cudaGetSymbolAddress((void**)&Y, g_Y);
    cudaGetSymbolAddress((void**)&ssel, g_ssel);
    cudaGetSymbolAddress((void**)&dstv, g_dst);
    cudaGetSymbolAddress((void**)&eidx, g_eidx);
    cudaGetSymbolAddress((void**)&cnt, g_cnt);
    cudaGetSymbolAddress((void**)&rowptr, g_rowptr);
    cudaGetSymbolAddress((void**)&cursor, g_cursor);
    cudaGetSymbolAddress((void**)&pre, g_pre);
    cudaGetSymbolAddress((void**)&bsum, g_bsum);

    const int EB = (E_TR + 255) / 256;
    const int NB = (NNODES + 255) / 256;

    // ncu captures the 5th graph node -> keep encode_k<512> there.
    cudaMemsetAsync(cnt, 0, NNODES * sizeof(int));                       // 1
    hist_k<<<EB, 256>>>(tei, tet, ssel, dstv, cnt);                      // 2
    scan1_k<<<NBLK_SCAN, 256>>>(cnt, pre, bsum);                         // 3
    scan2_k<<<1, 256>>>(bsum, NBLK_SCAN);                                // 4
    encode_k<512><<<(N_PAPER + 255) / 256, 256>>>(x_paper, tp_w, tp_b, x0, N_PAPER);  // 5 <- profiled
    encode_k<128><<<(N_MESH + 255) / 256, 256>>>(x_mesh, tm_w, tm_b,
                                                 x0 + (size_t)N_PAPER * 16, N_MESH);  // 6
    scan3_k<<<NB, 256>>>(pre, bsum, rowptr, cursor);                     // 7
    scatter_k<<<EB, 256>>>(ssel, dstv, cursor, eidx);                    // 8

    // ---- layer 1: 16 -> 32, relu ----
    transform3_k<16, 32><<<NB, 256>>>(x0, comp1, basis1, root1, bias1, Y, x1);
    agg_csr_k<32, true><<<(NNODES * 8 + 255) / 256, 256>>>(rowptr, cnt, eidx, Y, x1);

    // ---- layer 2: 32 -> 32, relu ----
    transform3_k<32, 32><<<NB, 256>>>(x1, comp2, basis2, root2, bias2, Y, x0);
    agg_csr_k<32, true><<<(NNODES * 8 + 255) / 256, 256>>>(rowptr, cnt, eidx, Y, x0);

    // ---- layer 3: 32 -> 16, no relu -> z in x1 ----
    transform3_k<32, 16><<<NB, 256>>>(x0, comp3, basis3, root3, bias3, Y, x1);
    agg_csr_k<16, false><<<(NNODES * 4 + 255) / 256, 256>>>(rowptr, cnt, eidx, Y, x1);

    // ---- decode: merged pos+neg ----
    decode_k<<<(E_P + E_N + 255) / 256, 256>>>(pei, pet, nei, net, x1,
                                               dpp_w, dpp_b, dpm_w, dpm_b, out);
}

// round 13
// speedup vs baseline: 1.2936x; 1.0197x over previous
#include <cuda_runtime.h>

static const int N_PAPER = 200000;
static const int N_MESH  = 30000;
static const int NNODES  = 230000;
static const int E_TR    = 2000000;
static const int E_P     = 500000;
static const int E_N     = 500000;
static const int NBLK_SCAN = (NNODES + 1023) / 1024;   // 225

typedef unsigned long long u64;

// ---- static device scratch ----
__device__ __align__(256) float g_x0[NNODES * 32];
__device__ __align__(256) float g_x1[NNODES * 32];
__device__ __align__(256) float g_Y[2 * NNODES * 32];   // [Y_rel0 ; Y_rel1]
__device__ __align__(256) int   g_ssel[E_TR];           // src + etype*NNODES
__device__ __align__(256) int   g_dst[E_TR];
__device__ __align__(256) int   g_eidx[E_TR];           // CSR buckets (ssel by dst)
__device__ __align__(256) int   g_cnt[NNODES];
__device__ __align__(256) int   g_rowptr[NNODES];
__device__ __align__(256) int   g_cursor[NNODES];
__device__ __align__(256) int   g_pre[NNODES];
__device__ __align__(256) int   g_bsum[NBLK_SCAN];

// ---- packed f32x2 helpers (FFMA2 is PTX-only) ----
__device__ __forceinline__ u64 pack2(float a, float b) {
    u64 r;
    asm("mov.b64 %0, {%1, %2};" : "=l"(r) : "r"(__float_as_uint(a)), "r"(__float_as_uint(b)));
    return r;
}
__device__ __forceinline__ u64 ffma2(u64 a, u64 b, u64 c) {
    u64 d;
    asm("fma.rn.f32x2 %0, %1, %2, %3;" : "=l"(d) : "l"(a), "l"(b), "l"(c));
    return d;
}
__device__ __forceinline__ float2 unpack2(u64 v) {
    unsigned lo, hi;
    asm("mov.b64 {%0, %1}, %2;" : "=r"(lo), "=r"(hi) : "l"(v));
    return make_float2(__uint_as_float(lo), __uint_as_float(hi));
}

// ---- cp.async helpers ----
__device__ __forceinline__ unsigned sptr(const void* p) {
    return (unsigned)__cvta_generic_to_shared(p);
}
__device__ __forceinline__ void cpa16(unsigned dst, const void* src, int src_sz) {
    asm volatile("cp.async.cg.shared.global [%0], [%1], 16, %2;"
                 :: "r"(dst), "l"(src), "r"(src_sz));
}
__device__ __forceinline__ void cpa_commit() { asm volatile("cp.async.commit_group;"); }
__device__ __forceinline__ void cpa_wait1()  { asm volatile("cp.async.wait_group 1;"); }
__device__ __forceinline__ void cpa_wait0()  { asm volatile("cp.async.wait_group 0;"); }

// ---- CSR build ----
__global__ void hist_k(const int* __restrict__ ei, const int* __restrict__ et,
                       int* __restrict__ ssel, int* __restrict__ dstv, int* __restrict__ cnt)
{
    int e = blockIdx.x * blockDim.x + threadIdx.x;
    if (e >= E_TR) return;
    int s = ei[e];
    int d = ei[E_TR + e];
    int t = et[e];
    ssel[e] = s + t * NNODES;
    dstv[e] = d;
    atomicAdd(&cnt[d], 1);
}

__global__ void scan1_k(const int* __restrict__ cnt, int* __restrict__ pre, int* __restrict__ bsum)
{
    __shared__ int sh[256];
    int tid = threadIdx.x;
    int base = blockIdx.x * 1024 + tid * 4;
    int v[4];
#pragma unroll
    for (int j = 0; j < 4; j++) v[j] = (base + j < NNODES) ? cnt[base + j] : 0;
    int tsum = v[0] + v[1] + v[2] + v[3];
    sh[tid] = tsum;
    __syncthreads();
    for (int off = 1; off < 256; off <<= 1) {
        int t = (tid >= off) ? sh[tid - off] : 0;
        __syncthreads();
        sh[tid] += t;
        __syncthreads();
    }
    int run = sh[tid] - tsum;
#pragma unroll
    for (int j = 0; j < 4; j++) {
        if (base + j < NNODES) pre[base + j] = run;
        run += v[j];
    }
    if (tid == 255) bsum[blockIdx.x] = sh[255];
}

__global__ void scan2_k(int* __restrict__ bsum, int nb)
{
    __shared__ int sh[256];
    int tid = threadIdx.x;
    int v = (tid < nb) ? bsum[tid] : 0;
    sh[tid] = v;
    __syncthreads();
    for (int off = 1; off < 256; off <<= 1) {
        int t = (tid >= off) ? sh[tid - off] : 0;
        __syncthreads();
        sh[tid] += t;
        __syncthreads();
    }
    if (tid < nb) bsum[tid] = sh[tid] - v;
}

__global__ void scan3_k(const int* __restrict__ pre, const int* __restrict__ bsum,
                        int* __restrict__ rowptr, int* __restrict__ cursor)
{
    int n = blockIdx.x * blockDim.x + threadIdx.x;
    if (n >= NNODES) return;
    int rp = pre[n] + bsum[n >> 10];
    rowptr[n] = rp;
    cursor[n] = rp;
}

__global__ void scatter_k(const int* __restrict__ ssel, const int* __restrict__ dstv,
                          int* __restrict__ cursor, int* __restrict__ eidx)
{
    int e = blockIdx.x * blockDim.x + threadIdx.x;
    if (e >= E_TR) return;
    int pos = atomicAdd(&cursor[dstv[e]], 1);
    eidx[pos] = ssel[e];
}

// ---- encode: row-per-thread, cp.async.16 double-buffered KC=32 chunks,
//      float4-swizzled tile (c4 ^ (r&7)) read via LDS.128 (r12 winner) ----
template<int DIN>
__global__ void __launch_bounds__(256, 3) encode_k(const float* __restrict__ x,
                                                   const float* __restrict__ W,
                                                   const float* __restrict__ b,
                                                   float* __restrict__ out, int nrows)
{
    constexpr int KC = 32;
    constexpr int NCHUNK = DIN / KC;
    __shared__ float4 xt[2][256 * 8];        // [buf][row*8 + (c4 ^ (row&7))]
    __shared__ ulonglong2 Wc[2][KC * 4];
    __shared__ float bs[16];
    const ulonglong2* Wg = (const ulonglong2*)W;
    if (threadIdx.x < 16) bs[threadIdx.x] = b[threadIdx.x];

    int tid = threadIdx.x;
    int rowBase = blockIdx.x * 256;
    int row = rowBase + tid;

    auto issue = [&](int ch) {
        int buf = ch & 1;
        if (tid < KC * 4)
            cpa16(sptr(&Wc[buf][tid]), Wg + (size_t)(ch * KC) * 4 + tid, 16);
#pragma unroll
        for (int i = 0; i < 8; i++) {
            int idx = i * 256 + tid;          // 2048 float4s: c4 fastest
            int r  = idx >> 3;
            int c4 = idx & 7;
            int gr = rowBase + r;
            int grc = (gr < nrows) ? gr : 0;
            cpa16(sptr(&xt[buf][r * 8 + (c4 ^ (r & 7))]),
                  x + (size_t)grc * DIN + ch * KC + c4 * 4,
                  (gr < nrows) ? 16 : 0);
        }
        cpa_commit();
    };

    issue(0);
    u64 acc[8];
#pragma unroll
    for (int p = 0; p < 8; p++) acc[p] = 0ull;

    int sw = tid & 7;
    for (int ch = 0; ch < NCHUNK; ch++) {
        __syncthreads();
        if (ch + 1 < NCHUNK) { issue(ch + 1); cpa_wait1(); }
        else                 { cpa_wait0(); }
        __syncthreads();
        int buf = ch & 1;
#pragma unroll
        for (int c4 = 0; c4 < 8; c4++) {
            float4 xv = xt[buf][tid * 8 + (c4 ^ sw)];
            float c[4] = {xv.x, xv.y, xv.z, xv.w};
#pragma unroll
            for (int j = 0; j < 4; j++) {
                int k = c4 * 4 + j;
                u64 xx = pack2(c[j], c[j]);
#pragma unroll
                for (int q = 0; q < 4; q++) {
                    ulonglong2 w = Wc[buf][k * 4 + q];
                    acc[2 * q]     = ffma2(xx, w.x, acc[2 * q]);
                    acc[2 * q + 1] = ffma2(xx, w.y, acc[2 * q + 1]);
                }
            }
        }
    }
    if (row >= nrows) return;
    float4* op = (float4*)(out + (size_t)row * 16);
#pragma unroll
    for (int q = 0; q < 4; q++) {
        float2 lo = unpack2(acc[2 * q]);
        float2 hi = unpack2(acc[2 * q + 1]);
        op[q] = make_float4(lo.x + bs[4 * q], lo.y + bs[4 * q + 1],
                            hi.x + bs[4 * q + 2], hi.y + bs[4 * q + 3]);
    }
}

// ---- fused node transform: W built in-CTA; matrices processed SEQUENTIALLY
//      (one acc set live -> ~84 regs instead of ~130) ----
template<int DIN, int DOUT>
__global__ void __launch_bounds__(256) transform3_k(const float* __restrict__ xin,
                                                    const float* __restrict__ comp,
                                                    const float* __restrict__ basis,
                                                    const float* __restrict__ root,
                                                    const float* __restrict__ bias,
                                                    float* __restrict__ Ycat,
                                                    float* __restrict__ selfout)
{
    constexpr int DO2 = DOUT / 2;
    constexpr int DO4 = DOUT / 4;
    constexpr int DIO = DIN * DOUT;
    __shared__ ulonglong2 Ws4[3 * DIN * DO4];
    __shared__ u64 bs2[DO2];
    float* Wf = (float*)Ws4;
    for (int i = threadIdx.x; i < 2 * DIO; i += blockDim.x) {
        int r = i / DIO, io = i % DIO;
        float s = 0.f;
#pragma unroll
        for (int bb = 0; bb < 4; bb++) s += comp[r * 4 + bb] * basis[bb * DIO + io];
        Wf[i] = s;
    }
    for (int i = threadIdx.x; i < DIO; i += blockDim.x) Wf[2 * DIO + i] = root[i];
    if (threadIdx.x < DO2) bs2[threadIdx.x] = ((const u64*)bias)[threadIdx.x];
    __syncthreads();
    int row = blockIdx.x * blockDim.x + threadIdx.x;
    if (row >= NNODES) return;
    float xr[DIN];
    const float4* xp = (const float4*)(xin + (size_t)row * DIN);
#pragma unroll
    for (int k4 = 0; k4 < DIN / 4; k4++) {
        float4 v = xp[k4];
        xr[4*k4] = v.x; xr[4*k4+1] = v.y; xr[4*k4+2] = v.z; xr[4*k4+3] = v.w;
    }
#pragma unroll 1
    for (int m = 0; m < 3; m++) {
        u64 a[DO2];
#pragma unroll
        for (int p = 0; p < DO2; p++) a[p] = (m == 2) ? bs2[p] : 0ull;
#pragma unroll
        for (int k = 0; k < DIN; k++) {
            u64 xx = pack2(xr[k], xr[k]);
#pragma unroll
            for (int o = 0; o < DO4; o++) {
                ulonglong2 w = Ws4[(m * DIN + k) * DO4 + o];
                a[2*o]   = ffma2(xx, w.x, a[2*o]);
                a[2*o+1] = ffma2(xx, w.y, a[2*o+1]);
            }
        }
        float* outp = (m == 0) ? (Ycat + (size_t)row * DOUT)
                    : (m == 1) ? (Ycat + (size_t)(NNODES + row) * DOUT)
                    : (selfout + (size_t)row * DOUT);
#pragma unroll
        for (int o = 0; o < DO4; o++) {
            float2 lo = unpack2(a[2*o]), hi = unpack2(a[2*o+1]);
            ((float4*)outp)[o] = make_float4(lo.x, lo.y, hi.x, hi.y);
        }
    }
}

// ---- CSR gather aggregation + fused finalize:
//      2 lanes-groups per node (even/odd edges) + shfl-xor reduce ----
template<int DOUT, bool RELU>
__global__ void __launch_bounds__(256) agg_csr_k(const int* __restrict__ rowptr,
                                                 const int* __restrict__ cnt,
                                                 const int* __restrict__ eidx,
                                                 const float* __restrict__ Y,
                                                 float* __restrict__ x)
{
    constexpr int DO4 = DOUT / 4;
    constexpr int GRP = DO4 * 2;
    int gid = blockIdx.x * blockDim.x + threadIdx.x;
    int n = gid / GRP;
    int lane = threadIdx.x & (GRP - 1);
    int j = lane & (DO4 - 1);
    int h = lane >> ( (DO4 == 8) ? 3 : 2 );   // 0 or 1
    if (n >= NNODES) return;
    int start = rowptr[n];
    int deg = cnt[n];
    const float4* Y4 = (const float4*)Y;
    float4 acc = make_float4(0.f, 0.f, 0.f, 0.f);
    int k = h;
    for (; k + 2 < deg; k += 4) {
        int r0 = eidx[start + k];
        int r1 = eidx[start + k + 2];
        float4 v0 = Y4[(size_t)r0 * DO4 + j];
        float4 v1 = Y4[(size_t)r1 * DO4 + j];
        acc.x += v0.x + v1.x; acc.y += v0.y + v1.y;
        acc.z += v0.z + v1.z; acc.w += v0.w + v1.w;
    }
    if (k < deg) {
        int r = eidx[start + k];
        float4 v = Y4[(size_t)r * DO4 + j];
        acc.x += v.x; acc.y += v.y; acc.z += v.z; acc.w += v.w;
    }
    // combine the even/odd halves
    acc.x += __shfl_xor_sync(0xffffffffu, acc.x, DO4);
    acc.y += __shfl_xor_sync(0xffffffffu, acc.y, DO4);
    acc.z += __shfl_xor_sync(0xffffffffu, acc.z, DO4);
    acc.w += __shfl_xor_sync(0xffffffffu, acc.w, DO4);
    if (h) return;
    float s = 1.0f / fmaxf((float)deg, 1.0f);
    float4* xp = (float4*)x + (size_t)n * DO4 + j;
    float4 v = *xp;
    v.x += acc.x * s; v.y += acc.y * s; v.z += acc.z * s; v.w += acc.w * s;
    if (RELU) {
        v.x = fmaxf(v.x, 0.f); v.y = fmaxf(v.y, 0.f);
        v.z = fmaxf(v.z, 0.f); v.w = fmaxf(v.w, 0.f);
    }
    *xp = v;
}

// ---- decode: merged pos+neg ----
__global__ void __launch_bounds__(256) decode_k(const int* __restrict__ pei,
                                                const int* __restrict__ pet,
                                                const int* __restrict__ nei,
                                                const int* __restrict__ net,
                                                const float* __restrict__ z,
                                                const float* __restrict__ w0, const float* __restrict__ b0,
                                                const float* __restrict__ w1, const float* __restrict__ b1,
                                                float* __restrict__ out)
{
    __shared__ float4 Ws[128];   // [2][16][4]
    __shared__ float bs[32];
    for (int i = threadIdx.x; i < 128; i += blockDim.x)
        Ws[i] = (i < 64) ? ((const float4*)w0)[i] : ((const float4*)w1)[i - 64];
    if (threadIdx.x < 32)
        bs[threadIdx.x] = (threadIdx.x < 16) ? b0[threadIdx.x] : b1[threadIdx.x - 16];
    __syncthreads();
    int g = blockIdx.x * blockDim.x + threadIdx.x;
    if (g >= E_P + E_N) return;
    const int* ei;
    const int* et;
    int e;
    if (g < E_P) { ei = pei; et = pet; e = g; }
    else         { ei = nei; et = net; e = g - E_P; }
    int s = ei[e];
    int d = ei[E_P + e];
    int t = et[e];
    const float4* zs4 = (const float4*)(z + (size_t)s * 16);
    const float4* zd4 = (const float4*)(z + (size_t)d * 16);
    float zs[16];
#pragma unroll
    for (int k4 = 0; k4 < 4; k4++) {
        float4 v = zs4[k4];
        zs[4*k4] = v.x; zs[4*k4+1] = v.y; zs[4*k4+2] = v.z; zs[4*k4+3] = v.w;
    }
    float4 zd[4];
#pragma unroll
    for (int k4 = 0; k4 < 4; k4++) zd[k4] = zd4[k4];
    int tb = t * 16;
    float4 acc[4];
#pragma unroll
    for (int o = 0; o < 4; o++) acc[o] = make_float4(bs[tb+4*o], bs[tb+4*o+1], bs[tb+4*o+2], bs[tb+4*o+3]);
#pragma unroll
    for (int k = 0; k < 16; k++) {
        float xv = zs[k];
#pragma unroll
        for (int o = 0; o < 4; o++) {
            float4 w = Ws[t * 64 + k * 4 + o];
            acc[o].x += xv * w.x; acc[o].y += xv * w.y;
            acc[o].z += xv * w.z; acc[o].w += xv * w.w;
        }
    }
    float sc = 0.f;
#pragma unroll
    for (int o = 0; o < 4; o++)
        sc += acc[o].x*zd[o].x + acc[o].y*zd[o].y + acc[o].z*zd[o].z + acc[o].w*zd[o].w;
    out[g] = sc;
}

extern "C" void kernel_launch(void* const* d_in, const int* in_sizes, int n_in,
                              void* d_out, int out_size)
{
    const float* x_paper = (const float*)d_in[0];
    const float* x_mesh  = (const float*)d_in[1];
    const float* tp_w = (const float*)d_in[2];
    const float* tp_b = (const float*)d_in[3];
    const float* tm_w = (const float*)d_in[4];
    const float* tm_b = (const float*)d_in[5];
    const float* comp1 = (const float*)d_in[6];
    const float* basis1 = (const float*)d_in[7];
    const float* root1 = (const float*)d_in[8];
    const float* bias1 = (const float*)d_in[9];
    const float* comp2 = (const float*)d_in[10];
    const float* basis2 = (const float*)d_in[11];
    const float* root2 = (const float*)d_in[12];
    const float* bias2 = (const float*)d_in[13];
    const float* comp3 = (const float*)d_in[14];
    const float* basis3 = (const float*)d_in[15];
    const float* root3 = (const float*)d_in[16];
    const float* bias3 = (const float*)d_in[17];
    const float* dpp_w = (const float*)d_in[18];
    const float* dpp_b = (const float*)d_in[19];
    const float* dpm_w = (const float*)d_in[20];
    const float* dpm_b = (const float*)d_in[21];
    const int* tei = (const int*)d_in[22];   // JAX x32: int32 arrays
    const int* tet = (const int*)d_in[23];
    const int* pei = (const int*)d_in[24];
    const int* pet = (const int*)d_in[25];
    const int* nei = (const int*)d_in[26];
    const int* net = (const int*)d_in[27];
    float* out = (float*)d_out;

    float *x0, *x1, *Y;
    int *ssel, *dstv, *eidx, *cnt, *rowptr, *cursor, *pre, *bsum;
    cudaGetSymbolAddress((void**)&x0, g_x0);
    cudaGetSymbolAddress((void**)&x1, g_x1);
    cudaGetSymbolAddress((void**)&Y, g_Y);
    cudaGetSymbolAddress((void**)&ssel, g_ssel);
    cudaGetSymbolAddress((void**)&dstv, g_dst);
    cudaGetSymbolAddress((void**)&eidx, g_eidx);
    cudaGetSymbolAddress((void**)&cnt, g_cnt);
    cudaGetSymbolAddress((void**)&rowptr, g_rowptr);
    cudaGetSymbolAddress((void**)&cursor, g_cursor);
    cudaGetSymbolAddress((void**)&pre, g_pre);
    cudaGetSymbolAddress((void**)&bsum, g_bsum);

    const int EB = (E_TR + 255) / 256;
    const int NB = (NNODES + 255) / 256;

    // ncu captures the 5th graph node -> keep encode_k<512> there.
    cudaMemsetAsync(cnt, 0, NNODES * sizeof(int));                       // 1
    hist_k<<<EB, 256>>>(tei, tet, ssel, dstv, cnt);                      // 2
    scan1_k<<<NBLK_SCAN, 256>>>(cnt, pre, bsum);                         // 3
    scan2_k<<<1, 256>>>(bsum, NBLK_SCAN);                                // 4
    encode_k<512><<<(N_PAPER + 255) / 256, 256>>>(x_paper, tp_w, tp_b, x0, N_PAPER);  // 5 <- profiled
    encode_k<128><<<(N_MESH + 255) / 256, 256>>>(x_mesh, tm_w, tm_b,
                                                 x0 + (size_t)N_PAPER * 16, N_MESH);  // 6
    scan3_k<<<NB, 256>>>(pre, bsum, rowptr, cursor);                     // 7
    scatter_k<<<EB, 256>>>(ssel, dstv, cursor, eidx);                    // 8

    // ---- layer 1: 16 -> 32, relu ----
    transform3_k<16, 32><<<NB, 256>>>(x0, comp1, basis1, root1, bias1, Y, x1);
    agg_csr_k<32, true><<<(NNODES * 16 + 255) / 256, 256>>>(rowptr, cnt, eidx, Y, x1);

    // ---- layer 2: 32 -> 32, relu ----
    transform3_k<32, 32><<<NB, 256>>>(x1, comp2, basis2, root2, bias2, Y, x0);
    agg_csr_k<32, true><<<(NNODES * 16 + 255) / 256, 256>>>(rowptr, cnt, eidx, Y, x0);

    // ---- layer 3: 32 -> 16, no relu -> z in x1 ----
    transform3_k<32, 16><<<NB, 256>>>(x0, comp3, basis3, root3, bias3, Y, x1);
    agg_csr_k<16, false><<<(NNODES * 8 + 255) / 256, 256>>>(rowptr, cnt, eidx, Y, x1);

    // ---- decode: merged pos+neg ----
    decode_k<<<(E_P + E_N + 255) / 256, 256>>>(pei, pet, nei, net, x1,
                                               dpp_w, dpp_b, dpm_w, dpm_b, out);
}

// round 14
// speedup vs baseline: 1.3831x; 1.0692x over previous
#include <cuda_runtime.h>

static const int N_PAPER = 200000;
static const int N_MESH  = 30000;
static const int NNODES  = 230000;
static const int E_TR    = 2000000;
static const int E_P     = 500000;
static const int E_N     = 500000;
static const int NBLK_SCAN = (NNODES + 1023) / 1024;   // 225

typedef unsigned long long u64;

// ---- static device scratch ----
__device__ __align__(256) float g_x0[NNODES * 32];
__device__ __align__(256) float g_x1[NNODES * 32];
__device__ __align__(256) float g_Y[2 * NNODES * 32];   // Y_rel cat / s0,s1 scratch
__device__ __align__(256) int   g_ssel[E_TR];           // src + etype*NNODES
__device__ __align__(256) int   g_dst[E_TR];
__device__ __align__(256) int   g_eidx[E_TR];           // CSR buckets (ssel by dst)
__device__ __align__(256) int   g_cnt[NNODES];
__device__ __align__(256) int   g_rowptr[NNODES];
__device__ __align__(256) int   g_cursor[NNODES];
__device__ __align__(256) int   g_pre[NNODES];
__device__ __align__(256) int   g_bsum[NBLK_SCAN];

// ---- packed f32x2 helpers (PTX-only ops) ----
__device__ __forceinline__ u64 pack2(float a, float b) {
    u64 r;
    asm("mov.b64 %0, {%1, %2};" : "=l"(r) : "r"(__float_as_uint(a)), "r"(__float_as_uint(b)));
    return r;
}
__device__ __forceinline__ u64 ffma2(u64 a, u64 b, u64 c) {
    u64 d;
    asm("fma.rn.f32x2 %0, %1, %2, %3;" : "=l"(d) : "l"(a), "l"(b), "l"(c));
    return d;
}
__device__ __forceinline__ u64 mul2(u64 a, u64 b) {
    u64 d;
    asm("mul.rn.f32x2 %0, %1, %2;" : "=l"(d) : "l"(a), "l"(b));
    return d;
}
__device__ __forceinline__ u64 add2(u64 a, u64 b) {
    u64 d;
    asm("add.rn.f32x2 %0, %1, %2;" : "=l"(d) : "l"(a), "l"(b));
    return d;
}
__device__ __forceinline__ float2 unpack2(u64 v) {
    unsigned lo, hi;
    asm("mov.b64 {%0, %1}, %2;" : "=r"(lo), "=r"(hi) : "l"(v));
    return make_float2(__uint_as_float(lo), __uint_as_float(hi));
}

// ---- cp.async helpers ----
__device__ __forceinline__ unsigned sptr(const void* p) {
    return (unsigned)__cvta_generic_to_shared(p);
}
__device__ __forceinline__ void cpa16(unsigned dst, const void* src, int src_sz) {
    asm volatile("cp.async.cg.shared.global [%0], [%1], 16, %2;"
                 :: "r"(dst), "l"(src), "r"(src_sz));
}
__device__ __forceinline__ void cpa_commit() { asm volatile("cp.async.commit_group;"); }
__device__ __forceinline__ void cpa_wait1()  { asm volatile("cp.async.wait_group 1;"); }
__device__ __forceinline__ void cpa_wait0()  { asm volatile("cp.async.wait_group 0;"); }

// ---- CSR build ----
__global__ void hist_k(const int* __restrict__ ei, const int* __restrict__ et,
                       int* __restrict__ ssel, int* __restrict__ dstv, int* __restrict__ cnt)
{
    int e = blockIdx.x * blockDim.x + threadIdx.x;
    if (e >= E_TR) return;
    int s = ei[e];
    int d = ei[E_TR + e];
    int t = et[e];
    ssel[e] = s + t * NNODES;
    dstv[e] = d;
    atomicAdd(&cnt[d], 1);
}

__global__ void scan1_k(const int* __restrict__ cnt, int* __restrict__ pre, int* __restrict__ bsum)
{
    __shared__ int sh[256];
    int tid = threadIdx.x;
    int base = blockIdx.x * 1024 + tid * 4;
    int v[4];
#pragma unroll
    for (int j = 0; j < 4; j++) v[j] = (base + j < NNODES) ? cnt[base + j] : 0;
    int tsum = v[0] + v[1] + v[2] + v[3];
    sh[tid] = tsum;
    __syncthreads();
    for (int off = 1; off < 256; off <<= 1) {
        int t = (tid >= off) ? sh[tid - off] : 0;
        __syncthreads();
        sh[tid] += t;
        __syncthreads();
    }
    int run = sh[tid] - tsum;
#pragma unroll
    for (int j = 0; j < 4; j++) {
        if (base + j < NNODES) pre[base + j] = run;
        run += v[j];
    }
    if (tid == 255) bsum[blockIdx.x] = sh[255];
}

__global__ void scan2_k(int* __restrict__ bsum, int nb)
{
    __shared__ int sh[256];
    int tid = threadIdx.x;
    int v = (tid < nb) ? bsum[tid] : 0;
    sh[tid] = v;
    __syncthreads();
    for (int off = 1; off < 256; off <<= 1) {
        int t = (tid >= off) ? sh[tid - off] : 0;
        __syncthreads();
        sh[tid] += t;
        __syncthreads();
    }
    if (tid < nb) bsum[tid] = sh[tid] - v;
}

__global__ void scan3_k(const int* __restrict__ pre, const int* __restrict__ bsum,
                        int* __restrict__ rowptr, int* __restrict__ cursor)
{
    int n = blockIdx.x * blockDim.x + threadIdx.x;
    if (n >= NNODES) return;
    int rp = pre[n] + bsum[n >> 10];
    rowptr[n] = rp;
    cursor[n] = rp;
}

__global__ void scatter_k(const int* __restrict__ ssel, const int* __restrict__ dstv,
                          int* __restrict__ cursor, int* __restrict__ eidx)
{
    int e = blockIdx.x * blockDim.x + threadIdx.x;
    if (e >= E_TR) return;
    int pos = atomicAdd(&cursor[dstv[e]], 1);
    eidx[pos] = ssel[e];
}

// ---- encode: cp.async.16 double-buffered KC=32 chunks (r12 winner) ----
template<int DIN>
__global__ void __launch_bounds__(256, 3) encode_k(const float* __restrict__ x,
                                                   const float* __restrict__ W,
                                                   const float* __restrict__ b,
                                                   float* __restrict__ out, int nrows)
{
    constexpr int KC = 32;
    constexpr int NCHUNK = DIN / KC;
    __shared__ float4 xt[2][256 * 8];        // [buf][row*8 + (c4 ^ (row&7))]
    __shared__ ulonglong2 Wc[2][KC * 4];
    __shared__ float bs[16];
    const ulonglong2* Wg = (const ulonglong2*)W;
    if (threadIdx.x < 16) bs[threadIdx.x] = b[threadIdx.x];

    int tid = threadIdx.x;
    int rowBase = blockIdx.x * 256;
    int row = rowBase + tid;

    auto issue = [&](int ch) {
        int buf = ch & 1;
        if (tid < KC * 4)
            cpa16(sptr(&Wc[buf][tid]), Wg + (size_t)(ch * KC) * 4 + tid, 16);
#pragma unroll
        for (int i = 0; i < 8; i++) {
            int idx = i * 256 + tid;
            int r  = idx >> 3;
            int c4 = idx & 7;
            int gr = rowBase + r;
            int grc = (gr < nrows) ? gr : 0;
            cpa16(sptr(&xt[buf][r * 8 + (c4 ^ (r & 7))]),
                  x + (size_t)grc * DIN + ch * KC + c4 * 4,
                  (gr < nrows) ? 16 : 0);
        }
        cpa_commit();
    };

    issue(0);
    u64 acc[8];
#pragma unroll
    for (int p = 0; p < 8; p++) acc[p] = 0ull;

    int sw = tid & 7;
    for (int ch = 0; ch < NCHUNK; ch++) {
        __syncthreads();
        if (ch + 1 < NCHUNK) { issue(ch + 1); cpa_wait1(); }
        else                 { cpa_wait0(); }
        __syncthreads();
        int buf = ch & 1;
#pragma unroll
        for (int c4 = 0; c4 < 8; c4++) {
            float4 xv = xt[buf][tid * 8 + (c4 ^ sw)];
            float c[4] = {xv.x, xv.y, xv.z, xv.w};
#pragma unroll
            for (int j = 0; j < 4; j++) {
                int k = c4 * 4 + j;
                u64 xx = pack2(c[j], c[j]);
#pragma unroll
                for (int q = 0; q < 4; q++) {
                    ulonglong2 w = Wc[buf][k * 4 + q];
                    acc[2 * q]     = ffma2(xx, w.x, acc[2 * q]);
                    acc[2 * q + 1] = ffma2(xx, w.y, acc[2 * q + 1]);
                }
            }
        }
    }
    if (row >= nrows) return;
    float4* op = (float4*)(out + (size_t)row * 16);
#pragma unroll
    for (int q = 0; q < 4; q++) {
        float2 lo = unpack2(acc[2 * q]);
        float2 hi = unpack2(acc[2 * q + 1]);
        op[q] = make_float4(lo.x + bs[4 * q], lo.y + bs[4 * q + 1],
                            hi.x + bs[4 * q + 2], hi.y + bs[4 * q + 3]);
    }
}

// ---- layer-1 aggregate-first: s_r[n] = sum of x0[src] over type-r in-edges ----
// 8 lanes per node: j = lane&3 (float4 column of the 16-wide row), h = lane>>2.
__global__ void __launch_bounds__(256) agg16_k(const int* __restrict__ rowptr,
                                               const int* __restrict__ cnt,
                                               const int* __restrict__ eidx,
                                               const float* __restrict__ x,
                                               float* __restrict__ s)
{
    int gid = blockIdx.x * blockDim.x + threadIdx.x;
    int n = gid >> 3;
    int lane = threadIdx.x & 7;
    int j = lane & 3;
    int h = lane >> 2;
    if (n >= NNODES) return;
    int start = rowptr[n];
    int deg = cnt[n];
    const float4* X4 = (const float4*)x;
    float4 a0 = make_float4(0.f, 0.f, 0.f, 0.f);
    float4 a1 = make_float4(0.f, 0.f, 0.f, 0.f);
    for (int k = h; k < deg; k += 2) {
        int e = eidx[start + k];
        int t = (e >= NNODES) ? 1 : 0;
        int src = e - t * NNODES;
        float m1 = (float)t, m0 = 1.0f - m1;
        float4 v = X4[(size_t)src * 4 + j];
        a0.x += v.x * m0; a0.y += v.y * m0; a0.z += v.z * m0; a0.w += v.w * m0;
        a1.x += v.x * m1; a1.y += v.y * m1; a1.z += v.z * m1; a1.w += v.w * m1;
    }
    a0.x += __shfl_xor_sync(0xffffffffu, a0.x, 4);
    a0.y += __shfl_xor_sync(0xffffffffu, a0.y, 4);
    a0.z += __shfl_xor_sync(0xffffffffu, a0.z, 4);
    a0.w += __shfl_xor_sync(0xffffffffu, a0.w, 4);
    a1.x += __shfl_xor_sync(0xffffffffu, a1.x, 4);
    a1.y += __shfl_xor_sync(0xffffffffu, a1.y, 4);
    a1.z += __shfl_xor_sync(0xffffffffu, a1.z, 4);
    a1.w += __shfl_xor_sync(0xffffffffu, a1.w, 4);
    if (h) return;
    float4* S4 = (float4*)s;
    S4[(size_t)n * 4 + j] = a0;
    S4[(size_t)(NNODES + n) * 4 + j] = a1;
}

// ---- layer-1 transform: x1 = relu((s0@W0 + s1@W1)*inv_deg + x0@root + bias) ----
__global__ void __launch_bounds__(256) transformL1_k(const float* __restrict__ s,
                                                     const float* __restrict__ xin,
                                                     const int* __restrict__ cnt,
                                                     const float* __restrict__ comp,
                                                     const float* __restrict__ basis,
                                                     const float* __restrict__ root,
                                                     const float* __restrict__ bias,
                                                     float* __restrict__ out)
{
    constexpr int DIN = 16, DOUT = 32;
    constexpr int DO2 = DOUT / 2, DO4 = DOUT / 4, DIO = DIN * DOUT;
    __shared__ ulonglong2 Ws4[3 * DIN * DO4];   // W0, W1, root
    __shared__ u64 bs2[DO2];
    float* Wf = (float*)Ws4;
    for (int i = threadIdx.x; i < 2 * DIO; i += blockDim.x) {
        int r = i / DIO, io = i % DIO;
        float v = 0.f;
#pragma unroll
        for (int bb = 0; bb < 4; bb++) v += comp[r * 4 + bb] * basis[bb * DIO + io];
        Wf[i] = v;
    }
    for (int i = threadIdx.x; i < DIO; i += blockDim.x) Wf[2 * DIO + i] = root[i];
    if (threadIdx.x < DO2) bs2[threadIdx.x] = ((const u64*)bias)[threadIdx.x];
    __syncthreads();
    int row = blockIdx.x * blockDim.x + threadIdx.x;
    if (row >= NNODES) return;

    float inv = 1.0f / fmaxf((float)cnt[row], 1.0f);
    u64 iv = pack2(inv, inv);

    u64 acc[DO2];
#pragma unroll
    for (int p = 0; p < DO2; p++) acc[p] = 0ull;
    // message part: s0 @ W0 + s1 @ W1
#pragma unroll 1
    for (int m = 0; m < 2; m++) {
        float sr[DIN];
        const float4* sp = (const float4*)(s + (size_t)(m * NNODES + row) * DIN);
#pragma unroll
        for (int k4 = 0; k4 < DIN / 4; k4++) {
            float4 v = sp[k4];
            sr[4*k4] = v.x; sr[4*k4+1] = v.y; sr[4*k4+2] = v.z; sr[4*k4+3] = v.w;
        }
#pragma unroll
        for (int k = 0; k < DIN; k++) {
            u64 xx = pack2(sr[k], sr[k]);
#pragma unroll
            for (int o = 0; o < DO4; o++) {
                ulonglong2 w = Ws4[(m * DIN + k) * DO4 + o];
                acc[2*o]   = ffma2(xx, w.x, acc[2*o]);
                acc[2*o+1] = ffma2(xx, w.y, acc[2*o+1]);
            }
        }
    }
#pragma unroll
    for (int p = 0; p < DO2; p++) acc[p] = mul2(acc[p], iv);
    // self part: x @ root + bias
    {
        float xr[DIN];
        const float4* xp = (const float4*)(xin + (size_t)row * DIN);
#pragma unroll
        for (int k4 = 0; k4 < DIN / 4; k4++) {
            float4 v = xp[k4];
            xr[4*k4] = v.x; xr[4*k4+1] = v.y; xr[4*k4+2] = v.z; xr[4*k4+3] = v.w;
        }
        u64 a2[DO2];
#pragma unroll
        for (int p = 0; p < DO2; p++) a2[p] = bs2[p];
#pragma unroll
        for (int k = 0; k < DIN; k++) {
            u64 xx = pack2(xr[k], xr[k]);
#pragma unroll
            for (int o = 0; o < DO4; o++) {
                ulonglong2 w = Ws4[(2 * DIN + k) * DO4 + o];
                a2[2*o]   = ffma2(xx, w.x, a2[2*o]);
                a2[2*o+1] = ffma2(xx, w.y, a2[2*o+1]);
            }
        }
#pragma unroll
        for (int p = 0; p < DO2; p++) acc[p] = add2(acc[p], a2[p]);
    }
    float4* op = (float4*)(out + (size_t)row * DOUT);
#pragma unroll
    for (int o = 0; o < DO4; o++) {
        float2 lo = unpack2(acc[2*o]), hi = unpack2(acc[2*o+1]);
        op[o] = make_float4(fmaxf(lo.x, 0.f), fmaxf(lo.y, 0.f),
                            fmaxf(hi.x, 0.f), fmaxf(hi.y, 0.f));
    }
}

// ---- fused node transform (layers 2,3): W built in-CTA; sequential matrices ----
template<int DIN, int DOUT>
__global__ void __launch_bounds__(256) transform3_k(const float* __restrict__ xin,
                                                    const float* __restrict__ comp,
                                                    const float* __restrict__ basis,
                                                    const float* __restrict__ root,
                                                    const float* __restrict__ bias,
                                                    float* __restrict__ Ycat,
                                                    float* __restrict__ selfout)
{
    constexpr int DO2 = DOUT / 2;
    constexpr int DO4 = DOUT / 4;
    constexpr int DIO = DIN * DOUT;
    __shared__ ulonglong2 Ws4[3 * DIN * DO4];
    __shared__ u64 bs2[DO2];
    float* Wf = (float*)Ws4;
    for (int i = threadIdx.x; i < 2 * DIO; i += blockDim.x) {
        int r = i / DIO, io = i % DIO;
        float s = 0.f;
#pragma unroll
        for (int bb = 0; bb < 4; bb++) s += comp[r * 4 + bb] * basis[bb * DIO + io];
        Wf[i] = s;
    }
    for (int i = threadIdx.x; i < DIO; i += blockDim.x) Wf[2 * DIO + i] = root[i];
    if (threadIdx.x < DO2) bs2[threadIdx.x] = ((const u64*)bias)[threadIdx.x];
    __syncthreads();
    int row = blockIdx.x * blockDim.x + threadIdx.x;
    if (row >= NNODES) return;
    float xr[DIN];
    const float4* xp = (const float4*)(xin + (size_t)row * DIN);
#pragma unroll
    for (int k4 = 0; k4 < DIN / 4; k4++) {
        float4 v = xp[k4];
        xr[4*k4] = v.x; xr[4*k4+1] = v.y; xr[4*k4+2] = v.z; xr[4*k4+3] = v.w;
    }
#pragma unroll 1
    for (int m = 0; m < 3; m++) {
        u64 a[DO2];
#pragma unroll
        for (int p = 0; p < DO2; p++) a[p] = (m == 2) ? bs2[p] : 0ull;
#pragma unroll
        for (int k = 0; k < DIN; k++) {
            u64 xx = pack2(xr[k], xr[k]);
#pragma unroll
            for (int o = 0; o < DO4; o++) {
                ulonglong2 w = Ws4[(m * DIN + k) * DO4 + o];
                a[2*o]   = ffma2(xx, w.x, a[2*o]);
                a[2*o+1] = ffma2(xx, w.y, a[2*o+1]);
            }
        }
        float* outp = (m == 0) ? (Ycat + (size_t)row * DOUT)
                    : (m == 1) ? (Ycat + (size_t)(NNODES + row) * DOUT)
                    : (selfout + (size_t)row * DOUT);
#pragma unroll
        for (int o = 0; o < DO4; o++) {
            float2 lo = unpack2(a[2*o]), hi = unpack2(a[2*o+1]);
            ((float4*)outp)[o] = make_float4(lo.x, lo.y, hi.x, hi.y);
        }
    }
}

// ---- CSR gather aggregation + fused finalize (layers 2,3) ----
template<int DOUT, bool RELU>
__global__ void __launch_bounds__(256) agg_csr_k(const int* __restrict__ rowptr,
                                                 const int* __restrict__ cnt,
                                                 const int* __restrict__ eidx,
                                                 const float* __restrict__ Y,
                                                 float* __restrict__ x)
{
    constexpr int DO4 = DOUT / 4;
    constexpr int GRP = DO4 * 2;
    int gid = blockIdx.x * blockDim.x + threadIdx.x;
    int n = gid / GRP;
    int lane = threadIdx.x & (GRP - 1);
    int j = lane & (DO4 - 1);
    int h = lane >> ( (DO4 == 8) ? 3 : 2 );
    if (n >= NNODES) return;
    int start = rowptr[n];
    int deg = cnt[n];
    const float4* Y4 = (const float4*)Y;
    float4 acc = make_float4(0.f, 0.f, 0.f, 0.f);
    int k = h;
    for (; k + 2 < deg; k += 4) {
        int r0 = eidx[start + k];
        int r1 = eidx[start + k + 2];
        float4 v0 = Y4[(size_t)r0 * DO4 + j];
        float4 v1 = Y4[(size_t)r1 * DO4 + j];
        acc.x += v0.x + v1.x; acc.y += v0.y + v1.y;
        acc.z += v0.z + v1.z; acc.w += v0.w + v1.w;
    }
    if (k < deg) {
        int r = eidx[start + k];
        float4 v = Y4[(size_t)r * DO4 + j];
        acc.x += v.x; acc.y += v.y; acc.z += v.z; acc.w += v.w;
    }
    acc.x += __shfl_xor_sync(0xffffffffu, acc.x, DO4);
    acc.y += __shfl_xor_sync(0xffffffffu, acc.y, DO4);
    acc.z += __shfl_xor_sync(0xffffffffu, acc.z, DO4);
    acc.w += __shfl_xor_sync(0xffffffffu, acc.w, DO4);
    if (h) return;
    float s = 1.0f / fmaxf((float)deg, 1.0f);
    float4* xp = (float4*)x + (size_t)n * DO4 + j;
    float4 v = *xp;
    v.x += acc.x * s; v.y += acc.y * s; v.z += acc.z * s; v.w += acc.w * s;
    if (RELU) {
        v.x = fmaxf(v.x, 0.f); v.y = fmaxf(v.y, 0.f);
        v.z = fmaxf(v.z, 0.f); v.w = fmaxf(v.w, 0.f);
    }
    *xp = v;
}

// ---- decode: merged pos+neg ----
__global__ void __launch_bounds__(256) decode_k(const int* __restrict__ pei,
                                                const int* __restrict__ pet,
                                                const int* __restrict__ nei,
                                                const int* __restrict__ net,
                                                const float* __restrict__ z,
                                                const float* __restrict__ w0, const float* __restrict__ b0,
                                                const float* __restrict__ w1, const float* __restrict__ b1,
                                                float* __restrict__ out)
{
    __shared__ float4 Ws[128];   // [2][16][4]
    __shared__ float bs[32];
    for (int i = threadIdx.x; i < 128; i += blockDim.x)
        Ws[i] = (i < 64) ? ((const float4*)w0)[i] : ((const float4*)w1)[i - 64];
    if (threadIdx.x < 32)
        bs[threadIdx.x] = (threadIdx.x < 16) ? b0[threadIdx.x] : b1[threadIdx.x - 16];
    __syncthreads();
    int g = blockIdx.x * blockDim.x + threadIdx.x;
    if (g >= E_P + E_N) return;
    const int* ei;
    const int* et;
    int e;
    if (g < E_P) { ei = pei; et = pet; e = g; }
    else         { ei = nei; et = net; e = g - E_P; }
    int s = ei[e];
    int d = ei[E_P + e];
    int t = et[e];
    const float4* zs4 = (const float4*)(z + (size_t)s * 16);
    const float4* zd4 = (const float4*)(z + (size_t)d * 16);
    float zs[16];
#pragma unroll
    for (int k4 = 0; k4 < 4; k4++) {
        float4 v = zs4[k4];
        zs[4*k4] = v.x; zs[4*k4+1] = v.y; zs[4*k4+2] = v.z; zs[4*k4+3] = v.w;
    }
    float4 zd[4];
#pragma unroll
    for (int k4 = 0; k4 < 4; k4++) zd[k4] = zd4[k4];
    int tb = t * 16;
    float4 acc[4];
#pragma unroll
    for (int o = 0; o < 4; o++) acc[o] = make_float4(bs[tb+4*o], bs[tb+4*o+1], bs[tb+4*o+2], bs[tb+4*o+3]);
#pragma unroll
    for (int k = 0; k < 16; k++) {
        float xv = zs[k];
#pragma unroll
        for (int o = 0; o < 4; o++) {
            float4 w = Ws[t * 64 + k * 4 + o];
            acc[o].x += xv * w.x; acc[o].y += xv * w.y;
            acc[o].z += xv * w.z; acc[o].w += xv * w.w;
        }
    }
    float sc = 0.f;
#pragma unroll
    for (int o = 0; o < 4; o++)
        sc += acc[o].x*zd[o].x + acc[o].y*zd[o].y + acc[o].z*zd[o].z + acc[o].w*zd[o].w;
    out[g] = sc;
}

extern "C" void kernel_launch(void* const* d_in, const int* in_sizes, int n_in,
                              void* d_out, int out_size)
{
    const float* x_paper = (const float*)d_in[0];
    const float* x_mesh  = (const float*)d_in[1];
    const float* tp_w = (const float*)d_in[2];
    const float* tp_b = (const float*)d_in[3];
    const float* tm_w = (const float*)d_in[4];
    const float* tm_b = (const float*)d_in[5];
    const float* comp1 = (const float*)d_in[6];
    const float* basis1 = (const float*)d_in[7];
    const float* root1 = (const float*)d_in[8];
    const float* bias1 = (const float*)d_in[9];
    const float* comp2 = (const float*)d_in[10];
    const float* basis2 = (const float*)d_in[11];
    const float* root2 = (const float*)d_in[12];
    const float* bias2 = (const float*)d_in[13];
    const float* comp3 = (const float*)d_in[14];
    const float* basis3 = (const float*)d_in[15];
    const float* root3 = (const float*)d_in[16];
    const float* bias3 = (const float*)d_in[17];
    const float* dpp_w = (const float*)d_in[18];
    const float* dpp_b = (const float*)d_in[19];
    const float* dpm_w = (const float*)d_in[20];
    const float* dpm_b = (const float*)d_in[21];
    const int* tei = (const int*)d_in[22];   // JAX x32: int32 arrays
    const int* tet = (const int*)d_in[23];
    const int* pei = (const int*)d_in[24];
    const int* pet = (const int*)d_in[25];
    const int* nei = (const int*)d_in[26];
    const int* net = (const int*)d_in[27];
    float* out = (float*)d_out;

    float *x0, *x1, *Y;
    int *ssel, *dstv, *eidx, *cnt, *rowptr, *cursor, *pre, *bsum;
    cudaGetSymbolAddress((void**)&x0, g_x0);
    cudaGetSymbolAddress((void**)&x1, g_x1);
    cudaGetSymbolAddress((void**)&Y, g_Y);
    cudaGetSymbolAddress((void**)&ssel, g_ssel);
    cudaGetSymbolAddress((void**)&dstv, g_dst);
    cudaGetSymbolAddress((void**)&eidx, g_eidx);
    cudaGetSymbolAddress((void**)&cnt, g_cnt);
    cudaGetSymbolAddress((void**)&rowptr, g_rowptr);
    cudaGetSymbolAddress((void**)&cursor, g_cursor);
    cudaGetSymbolAddress((void**)&pre, g_pre);
    cudaGetSymbolAddress((void**)&bsum, g_bsum);

    const int EB = (E_TR + 255) / 256;
    const int NB = (NNODES + 255) / 256;

    // ncu captures the 5th graph node -> keep encode_k<512> there.
    cudaMemsetAsync(cnt, 0, NNODES * sizeof(int));                       // 1
    hist_k<<<EB, 256>>>(tei, tet, ssel, dstv, cnt);                      // 2
    scan1_k<<<NBLK_SCAN, 256>>>(cnt, pre, bsum);                         // 3
    scan2_k<<<1, 256>>>(bsum, NBLK_SCAN);                                // 4
    encode_k<512><<<(N_PAPER + 255) / 256, 256>>>(x_paper, tp_w, tp_b, x0, N_PAPER);  // 5 <- profiled
    encode_k<128><<<(N_MESH + 255) / 256, 256>>>(x_mesh, tm_w, tm_b,
                                                 x0 + (size_t)N_PAPER * 16, N_MESH);  // 6
    scan3_k<<<NB, 256>>>(pre, bsum, rowptr, cursor);                     // 7
    scatter_k<<<EB, 256>>>(ssel, dstv, cursor, eidx);                    // 8

    // ---- layer 1 (16 -> 32, relu): aggregate x first, then transform ----
    agg16_k<<<(NNODES * 8 + 255) / 256, 256>>>(rowptr, cnt, eidx, x0, Y);
    transformL1_k<<<NB, 256>>>(Y, x0, cnt, comp1, basis1, root1, bias1, x1);

    // ---- layer 2: 32 -> 32, relu ----
    transform3_k<32, 32><<<NB, 256>>>(x1, comp2, basis2, root2, bias2, Y, x0);
    agg_csr_k<32, true><<<(NNODES * 16 + 255) / 256, 256>>>(rowptr, cnt, eidx, Y, x0);

    // ---- layer 3: 32 -> 16, no relu -> z in x1 ----
    transform3_k<32, 16><<<NB, 256>>>(x0, comp3, basis3, root3, bias3, Y, x1);
    agg_csr_k<16, false><<<(NNODES * 8 + 255) / 256, 256>>>(rowptr, cnt, eidx, Y, x1);

    // ---- decode: merged pos+neg ----
    decode_k<<<(E_P + E_N + 255) / 256, 256>>>(pei, pet, nei, net, x1,
                                               dpp_w, dpp_b, dpm_w, dpm_b, out);
}

// round 15
// speedup vs baseline: 1.4148x; 1.0229x over previous
#include <cuda_runtime.h>

static const int N_PAPER = 200000;
static const int N_MESH  = 30000;
static const int NNODES  = 230000;
static const int E_TR    = 2000000;
static const int E_P     = 500000;
static const int E_N     = 500000;
static const int NBLK_SCAN = (NNODES + 1023) / 1024;   // 225

static const int EB_SCAT = (E_TR + 255) / 256;          // 7813 scatter blocks
static const int EB_ENC512 = (N_PAPER + 255) / 256;     // 782
static const int EB_ENC128 = (N_MESH + 255) / 256;      // 118
static const int ENC_TOT = EB_ENC512 + EB_ENC128;       // 900
static const int FUSE_MIX = 9 * ENC_TOT;                // 8100: 1 encode per 9 bids
static const int FUSE_GRID = EB_SCAT + ENC_TOT;         // 8713
static const int DSM_BYTES = 65536 + 4096 + 64;         // xt + Wc + bs

typedef unsigned long long u64;

// ---- static device scratch ----
__device__ __align__(256) float g_x0[NNODES * 32];
__device__ __align__(256) float g_x1[NNODES * 32];
__device__ __align__(256) float g_Y[2 * NNODES * 32];   // Y_rel cat / s0,s1 scratch
__device__ __align__(256) int   g_ssel[E_TR];
__device__ __align__(256) int   g_dst[E_TR];
__device__ __align__(256) int   g_eidx[E_TR];
__device__ __align__(256) int   g_cnt[NNODES];
__device__ __align__(256) int   g_rowptr[NNODES];
__device__ __align__(256) int   g_cursor[NNODES];
__device__ __align__(256) int   g_pre[NNODES];
__device__ __align__(256) int   g_bsum[NBLK_SCAN];

// ---- packed f32x2 helpers (PTX-only ops) ----
__device__ __forceinline__ u64 pack2(float a, float b) {
    u64 r;
    asm("mov.b64 %0, {%1, %2};" : "=l"(r) : "r"(__float_as_uint(a)), "r"(__float_as_uint(b)));
    return r;
}
__device__ __forceinline__ u64 ffma2(u64 a, u64 b, u64 c) {
    u64 d;
    asm("fma.rn.f32x2 %0, %1, %2, %3;" : "=l"(d) : "l"(a), "l"(b), "l"(c));
    return d;
}
__device__ __forceinline__ u64 mul2(u64 a, u64 b) {
    u64 d;
    asm("mul.rn.f32x2 %0, %1, %2;" : "=l"(d) : "l"(a), "l"(b));
    return d;
}
__device__ __forceinline__ u64 add2(u64 a, u64 b) {
    u64 d;
    asm("add.rn.f32x2 %0, %1, %2;" : "=l"(d) : "l"(a), "l"(b));
    return d;
}
__device__ __forceinline__ float2 unpack2(u64 v) {
    unsigned lo, hi;
    asm("mov.b64 {%0, %1}, %2;" : "=r"(lo), "=r"(hi) : "l"(v));
    return make_float2(__uint_as_float(lo), __uint_as_float(hi));
}

// ---- cp.async helpers ----
__device__ __forceinline__ unsigned sptr(const void* p) {
    return (unsigned)__cvta_generic_to_shared(p);
}
__device__ __forceinline__ void cpa16(unsigned dst, const void* src, int src_sz) {
    asm volatile("cp.async.cg.shared.global [%0], [%1], 16, %2;"
                 :: "r"(dst), "l"(src), "r"(src_sz));
}
__device__ __forceinline__ void cpa_commit() { asm volatile("cp.async.commit_group;"); }
__device__ __forceinline__ void cpa_wait1()  { asm volatile("cp.async.wait_group 1;"); }
__device__ __forceinline__ void cpa_wait0()  { asm volatile("cp.async.wait_group 0;"); }

// ---- CSR build ----
__global__ void hist_k(const int* __restrict__ ei, const int* __restrict__ et,
                       int* __restrict__ ssel, int* __restrict__ dstv, int* __restrict__ cnt)
{
    int e = blockIdx.x * blockDim.x + threadIdx.x;
    if (e >= E_TR) return;
    int s = ei[e];
    int d = ei[E_TR + e];
    int t = et[e];
    ssel[e] = s + t * NNODES;
    dstv[e] = d;
    atomicAdd(&cnt[d], 1);
}

__global__ void scan1_k(const int* __restrict__ cnt, int* __restrict__ pre, int* __restrict__ bsum)
{
    __shared__ int sh[256];
    int tid = threadIdx.x;
    int base = blockIdx.x * 1024 + tid * 4;
    int v[4];
#pragma unroll
    for (int j = 0; j < 4; j++) v[j] = (base + j < NNODES) ? cnt[base + j] : 0;
    int tsum = v[0] + v[1] + v[2] + v[3];
    sh[tid] = tsum;
    __syncthreads();
    for (int off = 1; off < 256; off <<= 1) {
        int t = (tid >= off) ? sh[tid - off] : 0;
        __syncthreads();
        sh[tid] += t;
        __syncthreads();
    }
    int run = sh[tid] - tsum;
#pragma unroll
    for (int j = 0; j < 4; j++) {
        if (base + j < NNODES) pre[base + j] = run;
        run += v[j];
    }
    if (tid == 255) bsum[blockIdx.x] = sh[255];
}

// scan3': folds scan2 in — each block sums bsum[0..seg) itself (block b covers
// nodes [b*256,(b+1)*256) which lie in a single 1024-node segment seg = b>>2).
__global__ void scan3_k(const int* __restrict__ pre, const int* __restrict__ bsum,
                        int* __restrict__ rowptr, int* __restrict__ cursor)
{
    __shared__ int sh[256];
    int tid = threadIdx.x;
    int seg = blockIdx.x >> 2;
    sh[tid] = (tid < seg) ? bsum[tid] : 0;   // seg <= 224 < 256
    __syncthreads();
    for (int off = 128; off > 0; off >>= 1) {
        if (tid < off) sh[tid] += sh[tid + off];
        __syncthreads();
    }
    int base = sh[0];
    int n = blockIdx.x * 256 + tid;
    if (n >= NNODES) return;
    int rp = pre[n] + base;
    rowptr[n] = rp;
    cursor[n] = rp;
}

// ---- encode body (dynamic smem): cp.async.16 double-buffered KC=32 chunks ----
template<int DIN>
__device__ __forceinline__ void encode_body(char* dsm,
                                            const float* __restrict__ x,
                                            const float* __restrict__ W,
                                            const float* __restrict__ b,
                                            float* __restrict__ out, int nrows, int blk)
{
    constexpr int KC = 32;
    constexpr int NCHUNK = DIN / KC;
    float4* xt = (float4*)dsm;                          // [2][2048]
    ulonglong2* Wc = (ulonglong2*)(dsm + 65536);        // [2][128]
    float* bs = (float*)(dsm + 65536 + 4096);           // [16]
    const ulonglong2* Wg = (const ulonglong2*)W;
    if (threadIdx.x < 16) bs[threadIdx.x] = b[threadIdx.x];

    int tid = threadIdx.x;
    int rowBase = blk * 256;
    int row = rowBase + tid;

    auto issue = [&](int ch) {
        int buf = ch & 1;
        if (tid < KC * 4)
            cpa16(sptr(&Wc[buf * 128 + tid]), Wg + (size_t)(ch * KC) * 4 + tid, 16);
#pragma unroll
        for (int i = 0; i < 8; i++) {
            int idx = i * 256 + tid;
            int r  = idx >> 3;
            int c4 = idx & 7;
            int gr = rowBase + r;
            int grc = (gr < nrows) ? gr : 0;
            cpa16(sptr(&xt[buf * 2048 + r * 8 + (c4 ^ (r & 7))]),
                  x + (size_t)grc * DIN + ch * KC + c4 * 4,
                  (gr < nrows) ? 16 : 0);
        }
        cpa_commit();
    };

    issue(0);
    u64 acc[8];
#pragma unroll
    for (int p = 0; p < 8; p++) acc[p] = 0ull;

    int sw = tid & 7;
    for (int ch = 0; ch < NCHUNK; ch++) {
        __syncthreads();
        if (ch + 1 < NCHUNK) { issue(ch + 1); cpa_wait1(); }
        else                 { cpa_wait0(); }
        __syncthreads();
        int buf = ch & 1;
#pragma unroll
        for (int c4 = 0; c4 < 8; c4++) {
            float4 xv = xt[buf * 2048 + tid * 8 + (c4 ^ sw)];
            float c[4] = {xv.x, xv.y, xv.z, xv.w};
#pragma unroll
            for (int j = 0; j < 4; j++) {
                int k = c4 * 4 + j;
                u64 xx = pack2(c[j], c[j]);
#pragma unroll
                for (int q = 0; q < 4; q++) {
                    ulonglong2 w = Wc[buf * 128 + k * 4 + q];
                    acc[2 * q]     = ffma2(xx, w.x, acc[2 * q]);
                    acc[2 * q + 1] = ffma2(xx, w.y, acc[2 * q + 1]);
                }
            }
        }
    }
    if (row >= nrows) return;
    float4* op = (float4*)(out + (size_t)row * 16);
#pragma unroll
    for (int q = 0; q < 4; q++) {
        float2 lo = unpack2(acc[2 * q]);
        float2 hi = unpack2(acc[2 * q + 1]);
        op[q] = make_float4(lo.x + bs[4 * q], lo.y + bs[4 * q + 1],
                            hi.x + bs[4 * q + 2], hi.y + bs[4 * q + 3]);
    }
}

// ---- fused: scatter ∥ encode512 ∥ encode128, interleaved 1 encode per 9 bids ----
__global__ void __launch_bounds__(256, 3) fused_k(
    const int* __restrict__ ssel, const int* __restrict__ dstv,
    int* __restrict__ cursor, int* __restrict__ eidx,
    const float* __restrict__ xp, const float* __restrict__ tpw, const float* __restrict__ tpb,
    const float* __restrict__ xm, const float* __restrict__ tmw, const float* __restrict__ tmb,
    float* __restrict__ x0)
{
    extern __shared__ char dsm[];
    int bid = blockIdx.x;
    if (bid < FUSE_MIX && (bid % 9) == 8) {
        int eb = bid / 9;
        if (eb < EB_ENC512)
            encode_body<512>(dsm, xp, tpw, tpb, x0, N_PAPER, eb);
        else
            encode_body<128>(dsm, xm, tmw, tmb, x0 + (size_t)N_PAPER * 16, N_MESH,
                             eb - EB_ENC512);
    } else {
        int sb = (bid < FUSE_MIX) ? (bid - bid / 9) : (bid - ENC_TOT);
        int e = sb * 256 + threadIdx.x;
        if (e < E_TR) {
            int pos = atomicAdd(&cursor[dstv[e]], 1);
            eidx[pos] = ssel[e];
        }
    }
}

// ---- layer-1 aggregate-first: s_r[n] = sum of x0[src] over type-r in-edges ----
__global__ void __launch_bounds__(256) agg16_k(const int* __restrict__ rowptr,
                                               const int* __restrict__ cnt,
                                               const int* __restrict__ eidx,
                                               const float* __restrict__ x,
                                               float* __restrict__ s)
{
    int gid = blockIdx.x * blockDim.x + threadIdx.x;
    int n = gid >> 3;
    int lane = threadIdx.x & 7;
    int j = lane & 3;
    int h = lane >> 2;
    if (n >= NNODES) return;
    int start = rowptr[n];
    int deg = cnt[n];
    const float4* X4 = (const float4*)x;
    float4 a0 = make_float4(0.f, 0.f, 0.f, 0.f);
    float4 a1 = make_float4(0.f, 0.f, 0.f, 0.f);
    for (int k = h; k < deg; k += 2) {
        int e = eidx[start + k];
        int t = (e >= NNODES) ? 1 : 0;
        int src = e - t * NNODES;
        float m1 = (float)t, m0 = 1.0f - m1;
        float4 v = X4[(size_t)src * 4 + j];
        a0.x += v.x * m0; a0.y += v.y * m0; a0.z += v.z * m0; a0.w += v.w * m0;
        a1.x += v.x * m1; a1.y += v.y * m1; a1.z += v.z * m1; a1.w += v.w * m1;
    }
    a0.x += __shfl_xor_sync(0xffffffffu, a0.x, 4);
    a0.y += __shfl_xor_sync(0xffffffffu, a0.y, 4);
    a0.z += __shfl_xor_sync(0xffffffffu, a0.z, 4);
    a0.w += __shfl_xor_sync(0xffffffffu, a0.w, 4);
    a1.x += __shfl_xor_sync(0xffffffffu, a1.x, 4);
    a1.y += __shfl_xor_sync(0xffffffffu, a1.y, 4);
    a1.z += __shfl_xor_sync(0xffffffffu, a1.z, 4);
    a1.w += __shfl_xor_sync(0xffffffffu, a1.w, 4);
    if (h) return;
    float4* S4 = (float4*)s;
    S4[(size_t)n * 4 + j] = a0;
    S4[(size_t)(NNODES + n) * 4 + j] = a1;
}

// ---- layer-1 transform: x1 = relu((s0@W0 + s1@W1)*inv_deg + x0@root + bias) ----
__global__ void __launch_bounds__(256) transformL1_k(const float* __restrict__ s,
                                                     const float* __restrict__ xin,
                                                     const int* __restrict__ cnt,
                                                     const float* __restrict__ comp,
                                                     const float* __restrict__ basis,
                                                     const float* __restrict__ root,
                                                     const float* __restrict__ bias,
                                                     float* __restrict__ out)
{
    constexpr int DIN = 16, DOUT = 32;
    constexpr int DO2 = DOUT / 2, DO4 = DOUT / 4, DIO = DIN * DOUT;
    __shared__ ulonglong2 Ws4[3 * DIN * DO4];
    __shared__ u64 bs2[DO2];
    float* Wf = (float*)Ws4;
    for (int i = threadIdx.x; i < 2 * DIO; i += blockDim.x) {
        int r = i / DIO, io = i % DIO;
        float v = 0.f;
#pragma unroll
        for (int bb = 0; bb < 4; bb++) v += comp[r * 4 + bb] * basis[bb * DIO + io];
        Wf[i] = v;
    }
    for (int i = threadIdx.x; i < DIO; i += blockDim.x) Wf[2 * DIO + i] = root[i];
    if (threadIdx.x < DO2) bs2[threadIdx.x] = ((const u64*)bias)[threadIdx.x];
    __syncthreads();
    int row = blockIdx.x * blockDim.x + threadIdx.x;
    if (row >= NNODES) return;

    float inv = 1.0f / fmaxf((float)cnt[row], 1.0f);
    u64 iv = pack2(inv, inv);

    u64 acc[DO2];
#pragma unroll
    for (int p = 0; p < DO2; p++) acc[p] = 0ull;
#pragma unroll 1
    for (int m = 0; m < 2; m++) {
        float sr[DIN];
        const float4* sp = (const float4*)(s + (size_t)(m * NNODES + row) * DIN);
#pragma unroll
        for (int k4 = 0; k4 < DIN / 4; k4++) {
            float4 v = sp[k4];
            sr[4*k4] = v.x; sr[4*k4+1] = v.y; sr[4*k4+2] = v.z; sr[4*k4+3] = v.w;
        }
#pragma unroll
        for (int k = 0; k < DIN; k++) {
            u64 xx = pack2(sr[k], sr[k]);
#pragma unroll
            for (int o = 0; o < DO4; o++) {
                ulonglong2 w = Ws4[(m * DIN + k) * DO4 + o];
                acc[2*o]   = ffma2(xx, w.x, acc[2*o]);
                acc[2*o+1] = ffma2(xx, w.y, acc[2*o+1]);
            }
        }
    }
#pragma unroll
    for (int p = 0; p < DO2; p++) acc[p] = mul2(acc[p], iv);
    {
        float xr[DIN];
        const float4* xp = (const float4*)(xin + (size_t)row * DIN);
#pragma unroll
        for (int k4 = 0; k4 < DIN / 4; k4++) {
            float4 v = xp[k4];
            xr[4*k4] = v.x; xr[4*k4+1] = v.y; xr[4*k4+2] = v.z; xr[4*k4+3] = v.w;
        }
        u64 a2[DO2];
#pragma unroll
        for (int p = 0; p < DO2; p++) a2[p] = bs2[p];
#pragma unroll
        for (int k = 0; k < DIN; k++) {
            u64 xx = pack2(xr[k], xr[k]);
#pragma unroll
            for (int o = 0; o < DO4; o++) {
                ulonglong2 w = Ws4[(2 * DIN + k) * DO4 + o];
                a2[2*o]   = ffma2(xx, w.x, a2[2*o]);
                a2[2*o+1] = ffma2(xx, w.y, a2[2*o+1]);
            }
        }
#pragma unroll
        for (int p = 0; p < DO2; p++) acc[p] = add2(acc[p], a2[p]);
    }
    float4* op = (float4*)(out + (size_t)row * DOUT);
#pragma unroll
    for (int o = 0; o < DO4; o++) {
        float2 lo = unpack2(acc[2*o]), hi = unpack2(acc[2*o+1]);
        op[o] = make_float4(fmaxf(lo.x, 0.f), fmaxf(lo.y, 0.f),
                            fmaxf(hi.x, 0.f), fmaxf(hi.y, 0.f));
    }
}

// ---- fused node transform (layers 2,3): W built in-CTA; sequential matrices ----
template<int DIN, int DOUT>
__global__ void __launch_bounds__(256) transform3_k(const float* __restrict__ xin,
                                                    const float* __restrict__ comp,
                                                    const float* __restrict__ basis,
                                                    const float* __restrict__ root,
                                                    const float* __restrict__ bias,
                                                    float* __restrict__ Ycat,
                                                    float* __restrict__ selfout)
{
    constexpr int DO2 = DOUT / 2;
    constexpr int DO4 = DOUT / 4;
    constexpr int DIO = DIN * DOUT;
    __shared__ ulonglong2 Ws4[3 * DIN * DO4];
    __shared__ u64 bs2[DO2];
    float* Wf = (float*)Ws4;
    for (int i = threadIdx.x; i < 2 * DIO; i += blockDim.x) {
        int r = i / DIO, io = i % DIO;
        float s = 0.f;
#pragma unroll
        for (int bb = 0; bb < 4; bb++) s += comp[r * 4 + bb] * basis[bb * DIO + io];
        Wf[i] = s;
    }
    for (int i = threadIdx.x; i < DIO; i += blockDim.x) Wf[2 * DIO + i] = root[i];
    if (threadIdx.x < DO2) bs2[threadIdx.x] = ((const u64*)bias)[threadIdx.x];
    __syncthreads();
    int row = blockIdx.x * blockDim.x + threadIdx.x;
    if (row >= NNODES) return;
    float xr[DIN];
    const float4* xp = (const float4*)(xin + (size_t)row * DIN);
#pragma unroll
    for (int k4 = 0; k4 < DIN / 4; k4++) {
        float4 v = xp[k4];
        xr[4*k4] = v.x; xr[4*k4+1] = v.y; xr[4*k4+2] = v.z; xr[4*k4+3] = v.w;
    }
#pragma unroll 1
    for (int m = 0; m < 3; m++) {
        u64 a[DO2];
#pragma unroll
        for (int p = 0; p < DO2; p++) a[p] = (m == 2) ? bs2[p] : 0ull;
#pragma unroll
        for (int k = 0; k < DIN; k++) {
            u64 xx = pack2(xr[k], xr[k]);
#pragma unroll
            for (int o = 0; o < DO4; o++) {
                ulonglong2 w = Ws4[(m * DIN + k) * DO4 + o];
                a[2*o]   = ffma2(xx, w.x, a[2*o]);
                a[2*o+1] = ffma2(xx, w.y, a[2*o+1]);
            }
        }
        float* outp = (m == 0) ? (Ycat + (size_t)row * DOUT)
                    : (m == 1) ? (Ycat + (size_t)(NNODES + row) * DOUT)
                    : (selfout + (size_t)row * DOUT);
#pragma unroll
        for (int o = 0; o < DO4; o++) {
            float2 lo = unpack2(a[2*o]), hi = unpack2(a[2*o+1]);
            ((float4*)outp)[o] = make_float4(lo.x, lo.y, hi.x, hi.y);
        }
    }
}

// ---- CSR gather aggregation + fused finalize (layers 2,3) ----
template<int DOUT, bool RELU>
__global__ void __launch_bounds__(256) agg_csr_k(const int* __restrict__ rowptr,
                                                 const int* __restrict__ cnt,
                                                 const int* __restrict__ eidx,
                                                 const float* __restrict__ Y,
                                                 float* __restrict__ x)
{
    constexpr int DO4 = DOUT / 4;
    constexpr int GRP = DO4 * 2;
    int gid = blockIdx.x * blockDim.x + threadIdx.x;
    int n = gid / GRP;
    int lane = threadIdx.x & (GRP - 1);
    int j = lane & (DO4 - 1);
    int h = lane >> ( (DO4 == 8) ? 3 : 2 );
    if (n >= NNODES) return;
    int start = rowptr[n];
    int deg = cnt[n];
    const float4* Y4 = (const float4*)Y;
    float4 acc = make_float4(0.f, 0.f, 0.f, 0.f);
    int k = h;
    for (; k + 2 < deg; k += 4) {
        int r0 = eidx[start + k];
        int r1 = eidx[start + k + 2];
        float4 v0 = Y4[(size_t)r0 * DO4 + j];
        float4 v1 = Y4[(size_t)r1 * DO4 + j];
        acc.x += v0.x + v1.x; acc.y += v0.y + v1.y;
        acc.z += v0.z + v1.z; acc.w += v0.w + v1.w;
    }
    if (k < deg) {
        int r = eidx[start + k];
        float4 v = Y4[(size_t)r * DO4 + j];
        acc.x += v.x; acc.y += v.y; acc.z += v.z; acc.w += v.w;
    }
    acc.x += __shfl_xor_sync(0xffffffffu, acc.x, DO4);
    acc.y += __shfl_xor_sync(0xffffffffu, acc.y, DO4);
    acc.z += __shfl_xor_sync(0xffffffffu, acc.z, DO4);
    acc.w += __shfl_xor_sync(0xffffffffu, acc.w, DO4);
    if (h) return;
    float s = 1.0f / fmaxf((float)deg, 1.0f);
    float4* xp = (float4*)x + (size_t)n * DO4 + j;
    float4 v = *xp;
    v.x += acc.x * s; v.y += acc.y * s; v.z += acc.z * s; v.w += acc.w * s;
    if (RELU) {
        v.x = fmaxf(v.x, 0.f); v.y = fmaxf(v.y, 0.f);
        v.z = fmaxf(v.z, 0.f); v.w = fmaxf(v.w, 0.f);
    }
    *xp = v;
}

// ---- decode: merged pos+neg ----
__global__ void __launch_bounds__(256) decode_k(const int* __restrict__ pei,
                                                const int* __restrict__ pet,
                                                const int* __restrict__ nei,
                                                const int* __restrict__ net,
                                                const float* __restrict__ z,
                                                const float* __restrict__ w0, const float* __restrict__ b0,
                                                const float* __restrict__ w1, const float* __restrict__ b1,
                                                float* __restrict__ out)
{
    __shared__ float4 Ws[128];
    __shared__ float bs[32];
    for (int i = threadIdx.x; i < 128; i += blockDim.x)
        Ws[i] = (i < 64) ? ((const float4*)w0)[i] : ((const float4*)w1)[i - 64];
    if (threadIdx.x < 32)
        bs[threadIdx.x] = (threadIdx.x < 16) ? b0[threadIdx.x] : b1[threadIdx.x - 16];
    __syncthreads();
    int g = blockIdx.x * blockDim.x + threadIdx.x;
    if (g >= E_P + E_N) return;
    const int* ei;
    const int* et;
    int e;
    if (g < E_P) { ei = pei; et = pet; e = g; }
    else         { ei = nei; et = net; e = g - E_P; }
    int s = ei[e];
    int d = ei[E_P + e];
    int t = et[e];
    const float4* zs4 = (const float4*)(z + (size_t)s * 16);
    const float4* zd4 = (const float4*)(z + (size_t)d * 16);
    float zs[16];
#pragma unroll
    for (int k4 = 0; k4 < 4; k4++) {
        float4 v = zs4[k4];
        zs[4*k4] = v.x; zs[4*k4+1] = v.y; zs[4*k4+2] = v.z; zs[4*k4+3] = v.w;
    }
    float4 zd[4];
#pragma unroll
    for (int k4 = 0; k4 < 4; k4++) zd[k4] = zd4[k4];
    int tb = t * 16;
    float4 acc[4];
#pragma unroll
    for (int o = 0; o < 4; o++) acc[o] = make_float4(bs[tb+4*o], bs[tb+4*o+1], bs[tb+4*o+2], bs[tb+4*o+3]);
#pragma unroll
    for (int k = 0; k < 16; k++) {
        float xv = zs[k];
#pragma unroll
        for (int o = 0; o < 4; o++) {
            float4 w = Ws[t * 64 + k * 4 + o];
            acc[o].x += xv * w.x; acc[o].y += xv * w.y;
            acc[o].z += xv * w.z; acc[o].w += xv * w.w;
        }
    }
    float sc = 0.f;
#pragma unroll
    for (int o = 0; o < 4; o++)
        sc += acc[o].x*zd[o].x + acc[o].y*zd[o].y + acc[o].z*zd[o].z + acc[o].w*zd[o].w;
    out[g] = sc;
}

extern "C" void kernel_launch(void* const* d_in, const int* in_sizes, int n_in,
                              void* d_out, int out_size)
{
    const float* x_paper = (const float*)d_in[0];
    const float* x_mesh  = (const float*)d_in[1];
    const float* tp_w = (const float*)d_in[2];
    const float* tp_b = (const float*)d_in[3];
    const float* tm_w = (const float*)d_in[4];
    const float* tm_b = (const float*)d_in[5];
    const float* comp1 = (const float*)d_in[6];
    const float* basis1 = (const float*)d_in[7];
    const float* root1 = (const float*)d_in[8];
    const float* bias1 = (const float*)d_in[9];
    const float* comp2 = (const float*)d_in[10];
    const float* basis2 = (const float*)d_in[11];
    const float* root2 = (const float*)d_in[12];
    const float* bias2 = (const float*)d_in[13];
    const float* comp3 = (const float*)d_in[14];
    const float* basis3 = (const float*)d_in[15];
    const float* root3 = (const float*)d_in[16];
    const float* bias3 = (const float*)d_in[17];
    const float* dpp_w = (const float*)d_in[18];
    const float* dpp_b = (const float*)d_in[19];
    const float* dpm_w = (const float*)d_in[20];
    const float* dpm_b = (const float*)d_in[21];
    const int* tei = (const int*)d_in[22];   // JAX x32: int32 arrays
    const int* tet = (const int*)d_in[23];
    const int* pei = (const int*)d_in[24];
    const int* pet = (const int*)d_in[25];
    const int* nei = (const int*)d_in[26];
    const int* net = (const int*)d_in[27];
    float* out = (float*)d_out;

    float *x0, *x1, *Y;
    int *ssel, *dstv, *eidx, *cnt, *rowptr, *cursor, *pre, *bsum;
    cudaGetSymbolAddress((void**)&x0, g_x0);
    cudaGetSymbolAddress((void**)&x1, g_x1);
    cudaGetSymbolAddress((void**)&Y, g_Y);
    cudaGetSymbolAddress((void**)&ssel, g_ssel);
    cudaGetSymbolAddress((void**)&dstv, g_dst);
    cudaGetSymbolAddress((void**)&eidx, g_eidx);
    cudaGetSymbolAddress((void**)&cnt, g_cnt);
    cudaGetSymbolAddress((void**)&rowptr, g_rowptr);
    cudaGetSymbolAddress((void**)&cursor, g_cursor);
    cudaGetSymbolAddress((void**)&pre, g_pre);
    cudaGetSymbolAddress((void**)&bsum, g_bsum);

    const int EB = (E_TR + 255) / 256;
    const int NB = (NNODES + 255) / 256;

    cudaFuncSetAttribute(fused_k, cudaFuncAttributeMaxDynamicSharedMemorySize, DSM_BYTES);

    // Node order: ncu captures the 5th graph node -> fused_k (encode+scatter).
    cudaMemsetAsync(cnt, 0, NNODES * sizeof(int));                       // 1
    hist_k<<<EB, 256>>>(tei, tet, ssel, dstv, cnt);                      // 2
    scan1_k<<<NBLK_SCAN, 256>>>(cnt, pre, bsum);                         // 3
    scan3_k<<<NB, 256>>>(pre, bsum, rowptr, cursor);                     // 4 (scan2 folded in)
    fused_k<<<FUSE_GRID, 256, DSM_BYTES>>>(ssel, dstv, cursor, eidx,     // 5 <- profiled
                                           x_paper, tp_w, tp_b,
                                           x_mesh, tm_w, tm_b, x0);

    // ---- layer 1 (16 -> 32, relu): aggregate x first, then transform ----
    agg16_k<<<(NNODES * 8 + 255) / 256, 256>>>(rowptr, cnt, eidx, x0, Y);
    transformL1_k<<<NB, 256>>>(Y, x0, cnt, comp1, basis1, root1, bias1, x1);

    // ---- layer 2: 32 -> 32, relu ----
    transform3_k<32, 32><<<NB, 256>>>(x1, comp2, basis2, root2, bias2, Y, x0);
    agg_csr_k<32, true><<<(NNODES * 16 + 255) / 256, 256>>>(rowptr, cnt, eidx, Y, x0);

    // ---- layer 3: 32 -> 16, no relu -> z in x1 ----
    transform3_k<32, 16><<<NB, 256>>>(x0, comp3, basis3, root3, bias3, Y, x1);
    agg_csr_k<16, false><<<(NNODES * 8 + 255) / 256, 256>>>(rowptr, cnt, eidx, Y, x1);

    // ---- decode: merged pos+neg ----
    decode_k<<<(E_P + E_N + 255) / 256, 256>>>(pei, pet, nei, net, x1,
                                               dpp_w, dpp_b, dpm_w, dpm_b, out);
}

// round 16
// speedup vs baseline: 1.4691x; 1.0384x over previous
#include <cuda_runtime.h>

static const int N_PAPER = 200000;
static const int N_MESH  = 30000;
static const int NNODES  = 230000;
static const int E_TR    = 2000000;
static const int E_P     = 500000;
static const int E_N     = 500000;
static const int NBLK_SCAN = (NNODES + 1023) / 1024;   // 225

static const int EB_SCAT = (E_TR + 255) / 256;          // 7813 scatter blocks
static const int EB_ENC512 = (N_PAPER + 255) / 256;     // 782
static const int EB_ENC128 = (N_MESH + 255) / 256;      // 118
static const int ENC_TOT = EB_ENC512 + EB_ENC128;       // 900
static const int FUSE_MIX = 9 * ENC_TOT;                // 8100
static const int FUSE_GRID = EB_SCAT + ENC_TOT;         // 8713
static const int DSM_BYTES = 65536 + 4096 + 64;

typedef unsigned long long u64;

// ---- static device scratch ----
__device__ __align__(256) float g_x0[NNODES * 32];      // encode out (16-wide) / layer3 self+z (16-wide)
__device__ __align__(256) float g_x1[NNODES * 32];      // layer2 self + x2 (32-wide)
__device__ __align__(256) float g_s[NNODES * 32];       // layer-1 sums s0,s1 (2 x 16-wide)
__device__ __align__(256) float g_Y[2 * NNODES * 32];   // Y_rel cat
__device__ __align__(256) int   g_ssel[E_TR];
__device__ __align__(256) int   g_dst[E_TR];
__device__ __align__(256) int   g_eidx[E_TR];
__device__ __align__(256) int   g_cnt[NNODES];
__device__ __align__(256) int   g_rowptr[NNODES];
__device__ __align__(256) int   g_cursor[NNODES];
__device__ __align__(256) int   g_pre[NNODES];
__device__ __align__(256) int   g_bsum[NBLK_SCAN];

// ---- packed f32x2 helpers (PTX-only ops) ----
__device__ __forceinline__ u64 pack2(float a, float b) {
    u64 r;
    asm("mov.b64 %0, {%1, %2};" : "=l"(r) : "r"(__float_as_uint(a)), "r"(__float_as_uint(b)));
    return r;
}
__device__ __forceinline__ u64 ffma2(u64 a, u64 b, u64 c) {
    u64 d;
    asm("fma.rn.f32x2 %0, %1, %2, %3;" : "=l"(d) : "l"(a), "l"(b), "l"(c));
    return d;
}
__device__ __forceinline__ u64 mul2(u64 a, u64 b) {
    u64 d;
    asm("mul.rn.f32x2 %0, %1, %2;" : "=l"(d) : "l"(a), "l"(b));
    return d;
}
__device__ __forceinline__ u64 add2(u64 a, u64 b) {
    u64 d;
    asm("add.rn.f32x2 %0, %1, %2;" : "=l"(d) : "l"(a), "l"(b));
    return d;
}
__device__ __forceinline__ float2 unpack2(u64 v) {
    unsigned lo, hi;
    asm("mov.b64 {%0, %1}, %2;" : "=r"(lo), "=r"(hi) : "l"(v));
    return make_float2(__uint_as_float(lo), __uint_as_float(hi));
}

// ---- cp.async helpers ----
__device__ __forceinline__ unsigned sptr(const void* p) {
    return (unsigned)__cvta_generic_to_shared(p);
}
__device__ __forceinline__ void cpa16(unsigned dst, const void* src, int src_sz) {
    asm volatile("cp.async.cg.shared.global [%0], [%1], 16, %2;"
                 :: "r"(dst), "l"(src), "r"(src_sz));
}
__device__ __forceinline__ void cpa_commit() { asm volatile("cp.async.commit_group;"); }
__device__ __forceinline__ void cpa_wait1()  { asm volatile("cp.async.wait_group 1;"); }
__device__ __forceinline__ void cpa_wait0()  { asm volatile("cp.async.wait_group 0;"); }

// ---- CSR build ----
__global__ void hist_k(const int* __restrict__ ei, const int* __restrict__ et,
                       int* __restrict__ ssel, int* __restrict__ dstv, int* __restrict__ cnt)
{
    int e = blockIdx.x * blockDim.x + threadIdx.x;
    if (e >= E_TR) return;
    int s = ei[e];
    int d = ei[E_TR + e];
    int t = et[e];
    ssel[e] = s + t * NNODES;
    dstv[e] = d;
    atomicAdd(&cnt[d], 1);
}

__global__ void scan1_k(const int* __restrict__ cnt, int* __restrict__ pre, int* __restrict__ bsum)
{
    __shared__ int sh[256];
    int tid = threadIdx.x;
    int base = blockIdx.x * 1024 + tid * 4;
    int v[4];
#pragma unroll
    for (int j = 0; j < 4; j++) v[j] = (base + j < NNODES) ? cnt[base + j] : 0;
    int tsum = v[0] + v[1] + v[2] + v[3];
    sh[tid] = tsum;
    __syncthreads();
    for (int off = 1; off < 256; off <<= 1) {
        int t = (tid >= off) ? sh[tid - off] : 0;
        __syncthreads();
        sh[tid] += t;
        __syncthreads();
    }
    int run = sh[tid] - tsum;
#pragma unroll
    for (int j = 0; j < 4; j++) {
        if (base + j < NNODES) pre[base + j] = run;
        run += v[j];
    }
    if (tid == 255) bsum[blockIdx.x] = sh[255];
}

// scan3: folds scan2 in (block b in segment seg = b>>2 sums bsum[0..seg))
__global__ void scan3_k(const int* __restrict__ pre, const int* __restrict__ bsum,
                        int* __restrict__ rowptr, int* __restrict__ cursor)
{
    __shared__ int sh[256];
    int tid = threadIdx.x;
    int seg = blockIdx.x >> 2;
    sh[tid] = (tid < seg) ? bsum[tid] : 0;
    __syncthreads();
    for (int off = 128; off > 0; off >>= 1) {
        if (tid < off) sh[tid] += sh[tid + off];
        __syncthreads();
    }
    int base = sh[0];
    int n = blockIdx.x * 256 + tid;
    if (n >= NNODES) return;
    int rp = pre[n] + base;
    rowptr[n] = rp;
    cursor[n] = rp;
}

// ---- encode body (dynamic smem): cp.async.16 double-buffered KC=32 chunks ----
template<int DIN>
__device__ __forceinline__ void encode_body(char* dsm,
                                            const float* __restrict__ x,
                                            const float* __restrict__ W,
                                            const float* __restrict__ b,
                                            float* __restrict__ out, int nrows, int blk)
{
    constexpr int KC = 32;
    constexpr int NCHUNK = DIN / KC;
    float4* xt = (float4*)dsm;
    ulonglong2* Wc = (ulonglong2*)(dsm + 65536);
    float* bs = (float*)(dsm + 65536 + 4096);
    const ulonglong2* Wg = (const ulonglong2*)W;
    if (threadIdx.x < 16) bs[threadIdx.x] = b[threadIdx.x];

    int tid = threadIdx.x;
    int rowBase = blk * 256;
    int row = rowBase + tid;

    auto issue = [&](int ch) {
        int buf = ch & 1;
        if (tid < KC * 4)
            cpa16(sptr(&Wc[buf * 128 + tid]), Wg + (size_t)(ch * KC) * 4 + tid, 16);
#pragma unroll
        for (int i = 0; i < 8; i++) {
            int idx = i * 256 + tid;
            int r  = idx >> 3;
            int c4 = idx & 7;
            int gr = rowBase + r;
            int grc = (gr < nrows) ? gr : 0;
            cpa16(sptr(&xt[buf * 2048 + r * 8 + (c4 ^ (r & 7))]),
                  x + (size_t)grc * DIN + ch * KC + c4 * 4,
                  (gr < nrows) ? 16 : 0);
        }
        cpa_commit();
    };

    issue(0);
    u64 acc[8];
#pragma unroll
    for (int p = 0; p < 8; p++) acc[p] = 0ull;

    int sw = tid & 7;
    for (int ch = 0; ch < NCHUNK; ch++) {
        __syncthreads();
        if (ch + 1 < NCHUNK) { issue(ch + 1); cpa_wait1(); }
        else                 { cpa_wait0(); }
        __syncthreads();
        int buf = ch & 1;
#pragma unroll
        for (int c4 = 0; c4 < 8; c4++) {
            float4 xv = xt[buf * 2048 + tid * 8 + (c4 ^ sw)];
            float c[4] = {xv.x, xv.y, xv.z, xv.w};
#pragma unroll
            for (int j = 0; j < 4; j++) {
                int k = c4 * 4 + j;
                u64 xx = pack2(c[j], c[j]);
#pragma unroll
                for (int q = 0; q < 4; q++) {
                    ulonglong2 w = Wc[buf * 128 + k * 4 + q];
                    acc[2 * q]     = ffma2(xx, w.x, acc[2 * q]);
                    acc[2 * q + 1] = ffma2(xx, w.y, acc[2 * q + 1]);
                }
            }
        }
    }
    if (row >= nrows) return;
    float4* op = (float4*)(out + (size_t)row * 16);
#pragma unroll
    for (int q = 0; q < 4; q++) {
        float2 lo = unpack2(acc[2 * q]);
        float2 hi = unpack2(acc[2 * q + 1]);
        op[q] = make_float4(lo.x + bs[4 * q], lo.y + bs[4 * q + 1],
                            hi.x + bs[4 * q + 2], hi.y + bs[4 * q + 3]);
    }
}

// ---- fused: scatter ∥ encode512 ∥ encode128 ----
__global__ void __launch_bounds__(256, 3) fused_k(
    const int* __restrict__ ssel, const int* __restrict__ dstv,
    int* __restrict__ cursor, int* __restrict__ eidx,
    const float* __restrict__ xp, const float* __restrict__ tpw, const float* __restrict__ tpb,
    const float* __restrict__ xm, const float* __restrict__ tmw, const float* __restrict__ tmb,
    float* __restrict__ x0)
{
    extern __shared__ char dsm[];
    int bid = blockIdx.x;
    if (bid < FUSE_MIX && (bid % 9) == 8) {
        int eb = bid / 9;
        if (eb < EB_ENC512)
            encode_body<512>(dsm, xp, tpw, tpb, x0, N_PAPER, eb);
        else
            encode_body<128>(dsm, xm, tmw, tmb, x0 + (size_t)N_PAPER * 16, N_MESH,
                             eb - EB_ENC512);
    } else {
        int sb = (bid < FUSE_MIX) ? (bid - bid / 9) : (bid - ENC_TOT);
        int e = sb * 256 + threadIdx.x;
        if (e < E_TR) {
            int pos = atomicAdd(&cursor[dstv[e]], 1);
            eidx[pos] = ssel[e];
        }
    }
}

// ---- layer-1 aggregate-first: s_r[n] = sum of x0[src] over type-r in-edges ----
__global__ void __launch_bounds__(256) agg16_k(const int* __restrict__ rowptr,
                                               const int* __restrict__ cnt,
                                               const int* __restrict__ eidx,
                                               const float* __restrict__ x,
                                               float* __restrict__ s)
{
    int gid = blockIdx.x * blockDim.x + threadIdx.x;
    int n = gid >> 3;
    int lane = threadIdx.x & 7;
    int j = lane & 3;
    int h = lane >> 2;
    if (n >= NNODES) return;
    int start = rowptr[n];
    int deg = cnt[n];
    const float4* X4 = (const float4*)x;
    float4 a0 = make_float4(0.f, 0.f, 0.f, 0.f);
    float4 a1 = make_float4(0.f, 0.f, 0.f, 0.f);
    for (int k = h; k < deg; k += 2) {
        int e = eidx[start + k];
        int t = (e >= NNODES) ? 1 : 0;
        int src = e - t * NNODES;
        float m1 = (float)t, m0 = 1.0f - m1;
        float4 v = X4[(size_t)src * 4 + j];
        a0.x += v.x * m0; a0.y += v.y * m0; a0.z += v.z * m0; a0.w += v.w * m0;
        a1.x += v.x * m1; a1.y += v.y * m1; a1.z += v.z * m1; a1.w += v.w * m1;
    }
    a0.x += __shfl_xor_sync(0xffffffffu, a0.x, 4);
    a0.y += __shfl_xor_sync(0xffffffffu, a0.y, 4);
    a0.z += __shfl_xor_sync(0xffffffffu, a0.z, 4);
    a0.w += __shfl_xor_sync(0xffffffffu, a0.w, 4);
    a1.x += __shfl_xor_sync(0xffffffffu, a1.x, 4);
    a1.y += __shfl_xor_sync(0xffffffffu, a1.y, 4);
    a1.z += __shfl_xor_sync(0xffffffffu, a1.z, 4);
    a1.w += __shfl_xor_sync(0xffffffffu, a1.w, 4);
    if (h) return;
    float4* S4 = (float4*)s;
    S4[(size_t)n * 4 + j] = a0;
    S4[(size_t)(NNODES + n) * 4 + j] = a1;
}

// ---- fused layer1+layer2 transform:
//   x1 = relu((s0@W1_0 + s1@W1_1)*inv + x0@root1 + bias1)   (kept in registers)
//   Y2_r = x1 @ W2_r ; self2 = x1 @ root2 + bias2 ----
__global__ void __launch_bounds__(256) transformL12_k(
    const float* __restrict__ s, const float* __restrict__ xin,
    const int* __restrict__ cnt,
    const float* __restrict__ comp1, const float* __restrict__ basis1,
    const float* __restrict__ root1, const float* __restrict__ bias1,
    const float* __restrict__ comp2, const float* __restrict__ basis2,
    const float* __restrict__ root2, const float* __restrict__ bias2,
    float* __restrict__ Ycat, float* __restrict__ self2)
{
    // L1: DIN=16, DOUT=32 ; L2: DIN=32, DOUT=32
    __shared__ ulonglong2 W1s[3 * 16 * 8];   // W1_0, W1_1, root1 (6KB)
    __shared__ ulonglong2 W2s[3 * 32 * 8];   // W2_0, W2_1, root2 (12KB)
    __shared__ u64 b1s[16];
    __shared__ u64 b2s[16];
    {
        float* Wf = (float*)W1s;
        for (int i = threadIdx.x; i < 2 * 512; i += blockDim.x) {
            int r = i / 512, io = i % 512;
            float v = 0.f;
#pragma unroll
            for (int bb = 0; bb < 4; bb++) v += comp1[r * 4 + bb] * basis1[bb * 512 + io];
            Wf[i] = v;
        }
        for (int i = threadIdx.x; i < 512; i += blockDim.x) Wf[1024 + i] = root1[i];
        float* Wf2 = (float*)W2s;
        for (int i = threadIdx.x; i < 2 * 1024; i += blockDim.x) {
            int r = i / 1024, io = i % 1024;
            float v = 0.f;
#pragma unroll
            for (int bb = 0; bb < 4; bb++) v += comp2[r * 4 + bb] * basis2[bb * 1024 + io];
            Wf2[i] = v;
        }
        for (int i = threadIdx.x; i < 1024; i += blockDim.x) Wf2[2048 + i] = root2[i];
        if (threadIdx.x < 16) {
            b1s[threadIdx.x] = ((const u64*)bias1)[threadIdx.x];
            b2s[threadIdx.x] = ((const u64*)bias2)[threadIdx.x];
        }
    }
    __syncthreads();
    int row = blockIdx.x * blockDim.x + threadIdx.x;
    if (row >= NNODES) return;

    float inv = 1.0f / fmaxf((float)cnt[row], 1.0f);
    u64 iv = pack2(inv, inv);

    // ---- layer 1 ----
    u64 acc[16];
#pragma unroll
    for (int p = 0; p < 16; p++) acc[p] = 0ull;
#pragma unroll 1
    for (int m = 0; m < 2; m++) {
        float sr[16];
        const float4* sp = (const float4*)(s + (size_t)(m * NNODES + row) * 16);
#pragma unroll
        for (int k4 = 0; k4 < 4; k4++) {
            float4 v = sp[k4];
            sr[4*k4] = v.x; sr[4*k4+1] = v.y; sr[4*k4+2] = v.z; sr[4*k4+3] = v.w;
        }
#pragma unroll
        for (int k = 0; k < 16; k++) {
            u64 xx = pack2(sr[k], sr[k]);
#pragma unroll
            for (int o = 0; o < 8; o++) {
                ulonglong2 w = W1s[(m * 16 + k) * 8 + o];
                acc[2*o]   = ffma2(xx, w.x, acc[2*o]);
                acc[2*o+1] = ffma2(xx, w.y, acc[2*o+1]);
            }
        }
    }
#pragma unroll
    for (int p = 0; p < 16; p++) acc[p] = mul2(acc[p], iv);
    {
        float xr[16];
        const float4* xp = (const float4*)(xin + (size_t)row * 16);
#pragma unroll
        for (int k4 = 0; k4 < 4; k4++) {
            float4 v = xp[k4];
            xr[4*k4] = v.x; xr[4*k4+1] = v.y; xr[4*k4+2] = v.z; xr[4*k4+3] = v.w;
        }
        u64 a2[16];
#pragma unroll
        for (int p = 0; p < 16; p++) a2[p] = b1s[p];
#pragma unroll
        for (int k = 0; k < 16; k++) {
            u64 xx = pack2(xr[k], xr[k]);
#pragma unroll
            for (int o = 0; o < 8; o++) {
                ulonglong2 w = W1s[(2 * 16 + k) * 8 + o];
                a2[2*o]   = ffma2(xx, w.x, a2[2*o]);
                a2[2*o+1] = ffma2(xx, w.y, a2[2*o+1]);
            }
        }
#pragma unroll
        for (int p = 0; p < 16; p++) acc[p] = add2(acc[p], a2[p]);
    }
    // x1 row in registers (relu)
    float x1r[32];
#pragma unroll
    for (int p = 0; p < 16; p++) {
        float2 v = unpack2(acc[p]);
        x1r[2*p]   = fmaxf(v.x, 0.f);
        x1r[2*p+1] = fmaxf(v.y, 0.f);
    }

    // ---- layer 2: three matmuls over x1r ----
#pragma unroll 1
    for (int m = 0; m < 3; m++) {
        u64 a[16];
#pragma unroll
        for (int p = 0; p < 16; p++) a[p] = (m == 2) ? b2s[p] : 0ull;
#pragma unroll
        for (int k = 0; k < 32; k++) {
            u64 xx = pack2(x1r[k], x1r[k]);
#pragma unroll
            for (int o = 0; o < 8; o++) {
                ulonglong2 w = W2s[(m * 32 + k) * 8 + o];
                a[2*o]   = ffma2(xx, w.x, a[2*o]);
                a[2*o+1] = ffma2(xx, w.y, a[2*o+1]);
            }
        }
        float* outp = (m == 0) ? (Ycat + (size_t)row * 32)
                    : (m == 1) ? (Ycat + (size_t)(NNODES + row) * 32)
                    : (self2 + (size_t)row * 32);
#pragma unroll
        for (int o = 0; o < 8; o++) {
            float2 lo = unpack2(a[2*o]), hi = unpack2(a[2*o+1]);
            ((float4*)outp)[o] = make_float4(lo.x, lo.y, hi.x, hi.y);
        }
    }
}

// ---- node transform (layer 3): W built in-CTA; sequential matrices ----
template<int DIN, int DOUT>
__global__ void __launch_bounds__(256) transform3_k(const float* __restrict__ xin,
                                                    const float* __restrict__ comp,
                                                    const float* __restrict__ basis,
                                                    const float* __restrict__ root,
                                                    const float* __restrict__ bias,
                                                    float* __restrict__ Ycat,
                                                    float* __restrict__ selfout)
{
    constexpr int DO2 = DOUT / 2;
    constexpr int DO4 = DOUT / 4;
    constexpr int DIO = DIN * DOUT;
    __shared__ ulonglong2 Ws4[3 * DIN * DO4];
    __shared__ u64 bs2[DO2];
    float* Wf = (float*)Ws4;
    for (int i = threadIdx.x; i < 2 * DIO; i += blockDim.x) {
        int r = i / DIO, io = i % DIO;
        float s = 0.f;
#pragma unroll
        for (int bb = 0; bb < 4; bb++) s += comp[r * 4 + bb] * basis[bb * DIO + io];
        Wf[i] = s;
    }
    for (int i = threadIdx.x; i < DIO; i += blockDim.x) Wf[2 * DIO + i] = root[i];
    if (threadIdx.x < DO2) bs2[threadIdx.x] = ((const u64*)bias)[threadIdx.x];
    __syncthreads();
    int row = blockIdx.x * blockDim.x + threadIdx.x;
    if (row >= NNODES) return;
    float xr[DIN];
    const float4* xp = (const float4*)(xin + (size_t)row * DIN);
#pragma unroll
    for (int k4 = 0; k4 < DIN / 4; k4++) {
        float4 v = xp[k4];
        xr[4*k4] = v.x; xr[4*k4+1] = v.y; xr[4*k4+2] = v.z; xr[4*k4+3] = v.w;
    }
#pragma unroll 1
    for (int m = 0; m < 3; m++) {
        u64 a[DO2];
#pragma unroll
        for (int p = 0; p < DO2; p++) a[p] = (m == 2) ? bs2[p] : 0ull;
#pragma unroll
        for (int k = 0; k < DIN; k++) {
            u64 xx = pack2(xr[k], xr[k]);
#pragma unroll
            for (int o = 0; o < DO4; o++) {
                ulonglong2 w = Ws4[(m * DIN + k) * DO4 + o];
                a[2*o]   = ffma2(xx, w.x, a[2*o]);
                a[2*o+1] = ffma2(xx, w.y, a[2*o+1]);
            }
        }
        float* outp = (m == 0) ? (Ycat + (size_t)row * DOUT)
                    : (m == 1) ? (Ycat + (size_t)(NNODES + row) * DOUT)
                    : (selfout + (size_t)row * DOUT);
#pragma unroll
        for (int o = 0; o < DO4; o++) {
            float2 lo = unpack2(a[2*o]), hi = unpack2(a[2*o+1]);
            ((float4*)outp)[o] = make_float4(lo.x, lo.y, hi.x, hi.y);
        }
    }
}

// ---- CSR gather aggregation + fused finalize (layers 2,3) ----
template<int DOUT, bool RELU>
__global__ void __launch_bounds__(256) agg_csr_k(const int* __restrict__ rowptr,
                                                 const int* __restrict__ cnt,
                                                 const int* __restrict__ eidx,
                                                 const float* __restrict__ Y,
                                                 float* __restrict__ x)
{
    constexpr int DO4 = DOUT / 4;
    constexpr int GRP = DO4 * 2;
    int gid = blockIdx.x * blockDim.x + threadIdx.x;
    int n = gid / GRP;
    int lane = threadIdx.x & (GRP - 1);
    int j = lane & (DO4 - 1);
    int h = lane >> ( (DO4 == 8) ? 3 : 2 );
    if (n >= NNODES) return;
    int start = rowptr[n];
    int deg = cnt[n];
    const float4* Y4 = (const float4*)Y;
    float4 acc = make_float4(0.f, 0.f, 0.f, 0.f);
    int k = h;
    for (; k + 2 < deg; k += 4) {
        int r0 = eidx[start + k];
        int r1 = eidx[start + k + 2];
        float4 v0 = Y4[(size_t)r0 * DO4 + j];
        float4 v1 = Y4[(size_t)r1 * DO4 + j];
        acc.x += v0.x + v1.x; acc.y += v0.y + v1.y;
        acc.z += v0.z + v1.z; acc.w += v0.w + v1.w;
    }
    if (k < deg) {
        int r = eidx[start + k];
        float4 v = Y4[(size_t)r * DO4 + j];
        acc.x += v.x; acc.y += v.y; acc.z += v.z; acc.w += v.w;
    }
    acc.x += __shfl_xor_sync(0xffffffffu, acc.x, DO4);
    acc.y += __shfl_xor_sync(0xffffffffu, acc.y, DO4);
    acc.z += __shfl_xor_sync(0xffffffffu, acc.z, DO4);
    acc.w += __shfl_xor_sync(0xffffffffu, acc.w, DO4);
    if (h) return;
    float s = 1.0f / fmaxf((float)deg, 1.0f);
    float4* xp = (float4*)x + (size_t)n * DO4 + j;
    float4 v = *xp;
    v.x += acc.x * s; v.y += acc.y * s; v.z += acc.z * s; v.w += acc.w * s;
    if (RELU) {
        v.x = fmaxf(v.x, 0.f); v.y = fmaxf(v.y, 0.f);
        v.z = fmaxf(v.z, 0.f); v.w = fmaxf(v.w, 0.f);
    }
    *xp = v;
}

// ---- decode: merged pos+neg ----
__global__ void __launch_bounds__(256) decode_k(const int* __restrict__ pei,
                                                const int* __restrict__ pet,
                                                const int* __restrict__ nei,
                                                const int* __restrict__ net,
                                                const float* __restrict__ z,
                                                const float* __restrict__ w0, const float* __restrict__ b0,
                                                const float* __restrict__ w1, const float* __restrict__ b1,
                                                float* __restrict__ out)
{
    __shared__ float4 Ws[128];
    __shared__ float bs[32];
    for (int i = threadIdx.x; i < 128; i += blockDim.x)
        Ws[i] = (i < 64) ? ((const float4*)w0)[i] : ((const float4*)w1)[i - 64];
    if (threadIdx.x < 32)
        bs[threadIdx.x] = (threadIdx.x < 16) ? b0[threadIdx.x] : b1[threadIdx.x - 16];
    __syncthreads();
    int g = blockIdx.x * blockDim.x + threadIdx.x;
    if (g >= E_P + E_N) return;
    const int* ei;
    const int* et;
    int e;
    if (g < E_P) { ei = pei; et = pet; e = g; }
    else         { ei = nei; et = net; e = g - E_P; }
    int s = ei[e];
    int d = ei[E_P + e];
    int t = et[e];
    const float4* zs4 = (const float4*)(z + (size_t)s * 16);
    const float4* zd4 = (const float4*)(z + (size_t)d * 16);
    float zs[16];
#pragma unroll
    for (int k4 = 0; k4 < 4; k4++) {
        float4 v = zs4[k4];
        zs[4*k4] = v.x; zs[4*k4+1] = v.y; zs[4*k4+2] = v.z; zs[4*k4+3] = v.w;
    }
    float4 zd[4];
#pragma unroll
    for (int k4 = 0; k4 < 4; k4++) zd[k4] = zd4[k4];
    int tb = t * 16;
    float4 acc[4];
#pragma unroll
    for (int o = 0; o < 4; o++) acc[o] = make_float4(bs[tb+4*o], bs[tb+4*o+1], bs[tb+4*o+2], bs[tb+4*o+3]);
#pragma unroll
    for (int k = 0; k < 16; k++) {
        float xv = zs[k];
#pragma unroll
        for (int o = 0; o < 4; o++) {
            float4 w = Ws[t * 64 + k * 4 + o];
            acc[o].x += xv * w.x; acc[o].y += xv * w.y;
            acc[o].z += xv * w.z; acc[o].w += xv * w.w;
        }
    }
    float sc = 0.f;
#pragma unroll
    for (int o = 0; o < 4; o++)
        sc += acc[o].x*zd[o].x + acc[o].y*zd[o].y + acc[o].z*zd[o].z + acc[o].w*zd[o].w;
    out[g] = sc;
}

extern "C" void kernel_launch(void* const* d_in, const int* in_sizes, int n_in,
                              void* d_out, int out_size)
{
    const float* x_paper = (const float*)d_in[0];
    const float* x_mesh  = (const float*)d_in[1];
    const float* tp_w = (const float*)d_in[2];
    const float* tp_b = (const float*)d_in[3];
    const float* tm_w = (const float*)d_in[4];
    const float* tm_b = (const float*)d_in[5];
    const float* comp1 = (const float*)d_in[6];
    const float* basis1 = (const float*)d_in[7];
    const float* root1 = (const float*)d_in[8];
    const float* bias1 = (const float*)d_in[9];
    const float* comp2 = (const float*)d_in[10];
    const float* basis2 = (const float*)d_in[11];
    const float* root2 = (const float*)d_in[12];
    const float* bias2 = (const float*)d_in[13];
    const float* comp3 = (const float*)d_in[14];
    const float* basis3 = (const float*)d_in[15];
    const float* root3 = (const float*)d_in[16];
    const float* bias3 = (const float*)d_in[17];
    const float* dpp_w = (const float*)d_in[18];
    const float* dpp_b = (const float*)d_in[19];
    const float* dpm_w = (const float*)d_in[20];
    const float* dpm_b = (const float*)d_in[21];
    const int* tei = (const int*)d_in[22];   // JAX x32: int32 arrays
    const int* tet = (const int*)d_in[23];
    const int* pei = (const int*)d_in[24];
    const int* pet = (const int*)d_in[25];
    const int* nei = (const int*)d_in[26];
    const int* net = (const int*)d_in[27];
    float* out = (float*)d_out;

    float *x0, *x1, *sbuf, *Y;
    int *ssel, *dstv, *eidx, *cnt, *rowptr, *cursor, *pre, *bsum;
    cudaGetSymbolAddress((void**)&x0, g_x0);
    cudaGetSymbolAddress((void**)&x1, g_x1);
    cudaGetSymbolAddress((void**)&sbuf, g_s);
    cudaGetSymbolAddress((void**)&Y, g_Y);
    cudaGetSymbolAddress((void**)&ssel, g_ssel);
    cudaGetSymbolAddress((void**)&dstv, g_dst);
    cudaGetSymbolAddress((void**)&eidx, g_eidx);
    cudaGetSymbolAddress((void**)&cnt, g_cnt);
    cudaGetSymbolAddress((void**)&rowptr, g_rowptr);
    cudaGetSymbolAddress((void**)&cursor, g_cursor);
    cudaGetSymbolAddress((void**)&pre, g_pre);
    cudaGetSymbolAddress((void**)&bsum, g_bsum);

    const int EB = (E_TR + 255) / 256;
    const int NB = (NNODES + 255) / 256;

    cudaFuncSetAttribute(fused_k, cudaFuncAttributeMaxDynamicSharedMemorySize, DSM_BYTES);

    // Node order: ncu captures the 5th graph node -> fused_k.
    cudaMemsetAsync(cnt, 0, NNODES * sizeof(int));                       // 1
    hist_k<<<EB, 256>>>(tei, tet, ssel, dstv, cnt);                      // 2
    scan1_k<<<NBLK_SCAN, 256>>>(cnt, pre, bsum);                         // 3
    scan3_k<<<NB, 256>>>(pre, bsum, rowptr, cursor);                     // 4
    fused_k<<<FUSE_GRID, 256, DSM_BYTES>>>(ssel, dstv, cursor, eidx,     // 5 <- profiled
                                           x_paper, tp_w, tp_b,
                                           x_mesh, tm_w, tm_b, x0);

    // ---- layer 1+2 transform fused: s = agg of x0; x1 never materialized ----
    agg16_k<<<(NNODES * 8 + 255) / 256, 256>>>(rowptr, cnt, eidx, x0, sbuf);
    transformL12_k<<<NB, 256>>>(sbuf, x0, cnt,
                                comp1, basis1, root1, bias1,
                                comp2, basis2, root2, bias2, Y, x1);
    agg_csr_k<32, true><<<(NNODES * 16 + 255) / 256, 256>>>(rowptr, cnt, eidx, Y, x1);

    // ---- layer 3: 32 -> 16, no relu -> z in x0 ----
    transform3_k<32, 16><<<NB, 256>>>(x1, comp3, basis3, root3, bias3, Y, x0);
    agg_csr_k<16, false><<<(NNODES * 8 + 255) / 256, 256>>>(rowptr, cnt, eidx, Y, x0);

    // ---- decode: merged pos+neg (z = x0) ----
    decode_k<<<(E_P + E_N + 255) / 256, 256>>>(pei, pet, nei, net, x0,
                                               dpp_w, dpp_b, dpm_w, dpm_b, out);
}